// round 1
// baseline (speedup 1.0000x reference)
#include <cuda_runtime.h>

// Problem constants
constexpr int B_  = 8;
constexpr int C_  = 256;
constexpr int CI_ = 64;
constexpr int N_  = 4096;   // H*W = 64*64

// Scratch (device globals: allocation-free rule)
__device__ float d_theta[B_ * N_ * CI_];  // [b][n][ci]
__device__ float d_phi  [B_ * CI_ * N_];  // [b][ci][n]
__device__ float d_g    [B_ * N_ * CI_];  // [b][n][ci]
__device__ float d_y    [B_ * N_ * CI_];  // [b][n][ci]

// ---------------------------------------------------------------------------
// Kernel 1: fused 1x1-conv projections. grid = (N/64, B, 3proj), 256 thr.
// Computes a 64ci x 64n tile of W @ X for one projection.
// ---------------------------------------------------------------------------
__global__ __launch_bounds__(256) void proj_kernel(
    const float* __restrict__ x,
    const float* __restrict__ gw, const float* __restrict__ gb,
    const float* __restrict__ tw, const float* __restrict__ tb,
    const float* __restrict__ pw, const float* __restrict__ pb)
{
    const int nt = blockIdx.x;   // n tile (64 cols)
    const int b  = blockIdx.y;
    const int pj = blockIdx.z;   // 0 theta, 1 phi, 2 g

    const float* w;  const float* bias;
    if (pj == 0)      { w = tw; bias = tb; }
    else if (pj == 1) { w = pw; bias = pb; }
    else              { w = gw; bias = gb; }

    __shared__ float xs[64][68];  // [c][n]
    __shared__ float ws[64][68];  // [ci][c]

    const int tid = threadIdx.x;
    const int tx  = tid & 15;     // n group (4 cols)
    const int ty  = tid >> 4;     // ci group (4 rows)

    float acc[4][4];
    #pragma unroll
    for (int i = 0; i < 4; i++)
        #pragma unroll
        for (int j = 0; j < 4; j++) acc[i][j] = 0.f;

    const float* xb = x + (size_t)b * C_ * N_ + nt * 64;

    for (int cc = 0; cc < C_; cc += 64) {
        #pragma unroll
        for (int i = 0; i < 4; i++) {
            int r = ty + i * 16;
            *(float4*)&xs[r][tx * 4] =
                *(const float4*)(xb + (size_t)(cc + r) * N_ + tx * 4);
            *(float4*)&ws[r][tx * 4] =
                *(const float4*)(w + r * C_ + cc + tx * 4);
        }
        __syncthreads();

        #pragma unroll
        for (int k = 0; k < 64; k += 4) {
            float a[4][4], bb[4][4];
            #pragma unroll
            for (int i = 0; i < 4; i++)
                *(float4*)a[i] = *(const float4*)&ws[ty * 4 + i][k];
            #pragma unroll
            for (int kk = 0; kk < 4; kk++)
                *(float4*)bb[kk] = *(const float4*)&xs[k + kk][tx * 4];
            #pragma unroll
            for (int i = 0; i < 4; i++)
                #pragma unroll
                for (int kk = 0; kk < 4; kk++)
                    #pragma unroll
                    for (int j = 0; j < 4; j++)
                        acc[i][j] = fmaf(a[i][kk], bb[kk][j], acc[i][j]);
        }
        __syncthreads();
    }

    float bv[4];
    #pragma unroll
    for (int i = 0; i < 4; i++) bv[i] = bias[ty * 4 + i];

    if (pj == 1) {
        // phi layout [ci][n]
        float* out = d_phi + (size_t)b * CI_ * N_;
        #pragma unroll
        for (int i = 0; i < 4; i++) {
            float4 v = make_float4(acc[i][0] + bv[i], acc[i][1] + bv[i],
                                   acc[i][2] + bv[i], acc[i][3] + bv[i]);
            *(float4*)(out + (size_t)(ty * 4 + i) * N_ + nt * 64 + tx * 4) = v;
        }
    } else {
        // theta / g layout [n][ci]: transpose write, 4 consecutive ci per n
        float* out = (pj == 0 ? d_theta : d_g) + (size_t)b * N_ * CI_;
        #pragma unroll
        for (int j = 0; j < 4; j++) {
            float4 v = make_float4(acc[0][j] + bv[0], acc[1][j] + bv[1],
                                   acc[2][j] + bv[2], acc[3][j] + bv[3]);
            *(float4*)(out + (size_t)(nt * 64 + tx * 4 + j) * CI_ + ty * 4) = v;
        }
    }
}

// ---------------------------------------------------------------------------
// Kernel 2: streaming-softmax attention (flash style), fp32.
// grid = (N/64, B), 256 threads. 64-query-row tile, loop over 64 key tiles.
// Dynamic smem: th/ph/gs/sp tiles (64x68) + reduction scratch.
// ---------------------------------------------------------------------------
constexpr int ATTN_SMEM_FLOATS = 4 * 64 * 68 + 64 * 17 + 3 * 64;
constexpr int ATTN_SMEM_BYTES  = ATTN_SMEM_FLOATS * 4;

__global__ __launch_bounds__(256) void attn_kernel()
{
    extern __shared__ float smem[];
    float (*th)[68]  = (float(*)[68])(smem);
    float (*ph)[68]  = (float(*)[68])(smem + 64 * 68);
    float (*gs)[68]  = (float(*)[68])(smem + 2 * 64 * 68);
    float (*sp)[68]  = (float(*)[68])(smem + 3 * 64 * 68);
    float (*red)[17] = (float(*)[17])(smem + 4 * 64 * 68);
    float* rowm  = smem + 4 * 64 * 68 + 64 * 17;
    float* rowl  = rowm + 64;
    float* alpha = rowl + 64;

    const int nt  = blockIdx.x;
    const int b   = blockIdx.y;
    const int tid = threadIdx.x;
    const int tx  = tid & 15;
    const int ty  = tid >> 4;

    const float* thp = d_theta + ((size_t)b * N_ + nt * 64) * CI_;
    const float* php = d_phi + (size_t)b * CI_ * N_;
    const float* gp  = d_g   + (size_t)b * N_ * CI_;

    #pragma unroll
    for (int i = 0; i < 4; i++) {
        int r = ty + i * 16;
        *(float4*)&th[r][tx * 4] = *(const float4*)(thp + (size_t)r * CI_ + tx * 4);
    }
    if (tid < 64) { rowm[tid] = -1e30f; rowl[tid] = 0.f; }

    float ya[4][4];
    #pragma unroll
    for (int i = 0; i < 4; i++)
        #pragma unroll
        for (int j = 0; j < 4; j++) ya[i][j] = 0.f;

    __syncthreads();

    for (int kt = 0; kt < 64; kt++) {
        // load key/value tiles
        #pragma unroll
        for (int i = 0; i < 4; i++) {
            int r = ty + i * 16;
            *(float4*)&ph[r][tx * 4] =
                *(const float4*)(php + (size_t)r * N_ + kt * 64 + tx * 4);
            *(float4*)&gs[r][tx * 4] =
                *(const float4*)(gp + (size_t)(kt * 64 + r) * CI_ + tx * 4);
        }
        __syncthreads();

        // S = theta_tile @ phi_tile   (4x4 register tile per thread)
        float s[4][4];
        #pragma unroll
        for (int i = 0; i < 4; i++)
            #pragma unroll
            for (int j = 0; j < 4; j++) s[i][j] = 0.f;

        #pragma unroll
        for (int k = 0; k < 64; k += 4) {
            float a[4][4], bb[4][4];
            #pragma unroll
            for (int i = 0; i < 4; i++)
                *(float4*)a[i] = *(const float4*)&th[ty * 4 + i][k];
            #pragma unroll
            for (int kk = 0; kk < 4; kk++)
                *(float4*)bb[kk] = *(const float4*)&ph[k + kk][tx * 4];
            #pragma unroll
            for (int i = 0; i < 4; i++)
                #pragma unroll
                for (int kk = 0; kk < 4; kk++)
                    #pragma unroll
                    for (int j = 0; j < 4; j++)
                        s[i][j] = fmaf(a[i][kk], bb[kk][j], s[i][j]);
        }

        // per-row tile max partials
        #pragma unroll
        for (int i = 0; i < 4; i++) {
            float m = fmaxf(fmaxf(s[i][0], s[i][1]), fmaxf(s[i][2], s[i][3]));
            red[ty * 4 + i][tx] = m;
        }
        __syncthreads();

        if (tid < 64) {
            float m = red[tid][0];
            #pragma unroll
            for (int j = 1; j < 16; j++) m = fmaxf(m, red[tid][j]);
            float nm = fmaxf(rowm[tid], m);
            alpha[tid] = __expf(rowm[tid] - nm);
            rowm[tid] = nm;
        }
        __syncthreads();

        // exponentiate, write P, accumulate row sums, rescale accumulators
        #pragma unroll
        for (int i = 0; i < 4; i++) {
            int r = ty * 4 + i;
            float nm = rowm[r];
            float p0 = __expf(s[i][0] - nm);
            float p1 = __expf(s[i][1] - nm);
            float p2 = __expf(s[i][2] - nm);
            float p3 = __expf(s[i][3] - nm);
            *(float4*)&sp[r][tx * 4] = make_float4(p0, p1, p2, p3);
            red[r][tx] = p0 + p1 + p2 + p3;
            float al = alpha[r];
            #pragma unroll
            for (int j = 0; j < 4; j++) ya[i][j] *= al;
        }
        __syncthreads();

        if (tid < 64) {
            float ssum = 0.f;
            #pragma unroll
            for (int j = 0; j < 16; j++) ssum += red[tid][j];
            rowl[tid] = rowl[tid] * alpha[tid] + ssum;
        }

        // y += P @ g_tile
        #pragma unroll
        for (int m = 0; m < 64; m += 4) {
            float p[4][4], gv[4][4];
            #pragma unroll
            for (int i = 0; i < 4; i++)
                *(float4*)p[i] = *(const float4*)&sp[ty * 4 + i][m];
            #pragma unroll
            for (int mm = 0; mm < 4; mm++)
                *(float4*)gv[mm] = *(const float4*)&gs[m + mm][tx * 4];
            #pragma unroll
            for (int i = 0; i < 4; i++)
                #pragma unroll
                for (int mm = 0; mm < 4; mm++)
                    #pragma unroll
                    for (int j = 0; j < 4; j++)
                        ya[i][j] = fmaf(p[i][mm], gv[mm][j], ya[i][j]);
        }
        __syncthreads();
    }

    // normalize and store y [n][ci]
    float* yp = d_y + ((size_t)b * N_ + nt * 64) * CI_;
    #pragma unroll
    for (int i = 0; i < 4; i++) {
        int r = ty * 4 + i;
        float inv = 1.f / rowl[r];
        float4 v = make_float4(ya[i][0] * inv, ya[i][1] * inv,
                               ya[i][2] * inv, ya[i][3] * inv);
        *(float4*)(yp + (size_t)r * CI_ + tx * 4) = v;
    }
}

// ---------------------------------------------------------------------------
// Kernel 3: output 1x1 conv + residual. grid = (N/32, 2, B), 256 threads.
// out tile: 128 co x 32 n.
// ---------------------------------------------------------------------------
__global__ __launch_bounds__(256) void wconv_kernel(
    const float* __restrict__ x,
    const float* __restrict__ ww, const float* __restrict__ wb,
    float* __restrict__ out)
{
    const int nt = blockIdx.x;   // n tile of 32
    const int ct = blockIdx.y;   // co tile of 128
    const int b  = blockIdx.z;

    __shared__ float ys[32][68];   // [n][ci]
    __shared__ float ws[128][68];  // [co][ci]

    const int tid = threadIdx.x;
    {
        const int lx = tid & 15, ln = tid >> 4;
        const float* yb = d_y + ((size_t)b * N_ + nt * 32) * CI_;
        #pragma unroll
        for (int i = 0; i < 2; i++) {
            int n = ln + i * 16;
            *(float4*)&ys[n][lx * 4] = *(const float4*)(yb + (size_t)n * CI_ + lx * 4);
        }
        #pragma unroll
        for (int i = 0; i < 8; i++) {
            int co = ln + i * 16;
            *(float4*)&ws[co][lx * 4] =
                *(const float4*)(ww + (size_t)(ct * 128 + co) * CI_ + lx * 4);
        }
    }
    __syncthreads();

    const int tx = tid & 7;    // n group (4)
    const int ty = tid >> 3;   // co group (4), 0..31

    float acc[4][4];
    #pragma unroll
    for (int i = 0; i < 4; i++)
        #pragma unroll
        for (int j = 0; j < 4; j++) acc[i][j] = 0.f;

    #pragma unroll
    for (int k = 0; k < 64; k += 4) {
        float a[4][4], yv[4][4];
        #pragma unroll
        for (int i = 0; i < 4; i++)
            *(float4*)a[i] = *(const float4*)&ws[ty * 4 + i][k];
        #pragma unroll
        for (int j = 0; j < 4; j++)
            *(float4*)yv[j] = *(const float4*)&ys[tx * 4 + j][k];
        #pragma unroll
        for (int i = 0; i < 4; i++)
            #pragma unroll
            for (int j = 0; j < 4; j++)
                #pragma unroll
                for (int kk = 0; kk < 4; kk++)
                    acc[i][j] = fmaf(a[i][kk], yv[j][kk], acc[i][j]);
    }

    #pragma unroll
    for (int i = 0; i < 4; i++) {
        int co = ct * 128 + ty * 4 + i;
        float bv = wb[co];
        size_t base = ((size_t)b * C_ + co) * N_ + nt * 32 + tx * 4;
        float4 xv = *(const float4*)(x + base);
        float4 v = make_float4(acc[i][0] + bv + xv.x, acc[i][1] + bv + xv.y,
                               acc[i][2] + bv + xv.z, acc[i][3] + bv + xv.w);
        *(float4*)(out + base) = v;
    }
}

// ---------------------------------------------------------------------------
extern "C" void kernel_launch(void* const* d_in, const int* in_sizes, int n_in,
                              void* d_out, int out_size)
{
    const float* x  = (const float*)d_in[0];
    const float* gw = (const float*)d_in[1];
    const float* gb = (const float*)d_in[2];
    const float* tw = (const float*)d_in[3];
    const float* tb = (const float*)d_in[4];
    const float* pw = (const float*)d_in[5];
    const float* pb = (const float*)d_in[6];
    const float* ww = (const float*)d_in[7];
    const float* wb = (const float*)d_in[8];
    float* out = (float*)d_out;

    cudaFuncSetAttribute(attn_kernel,
                         cudaFuncAttributeMaxDynamicSharedMemorySize,
                         ATTN_SMEM_BYTES);

    proj_kernel<<<dim3(N_ / 64, B_, 3), 256>>>(x, gw, gb, tw, tb, pw, pb);
    attn_kernel<<<dim3(N_ / 64, B_), 256, ATTN_SMEM_BYTES>>>();
    wconv_kernel<<<dim3(N_ / 32, 2, B_), 256>>>(x, ww, wb, out);
}

// round 3
// speedup vs baseline: 2.0270x; 2.0270x over previous
#include <cuda_runtime.h>
#include <cuda_bf16.h>
#include <cstdint>

// Problem constants
constexpr int B_  = 8;
constexpr int C_  = 256;
constexpr int CI_ = 64;
constexpr int N_  = 4096;   // H*W

// Scratch (device globals: allocation-free rule)
__device__ float d_y[B_ * N_ * CI_];                 // attention output fp32 [b][n][ci]
__device__ __nv_bfloat16 d_th_hi[B_ * N_ * CI_];     // theta hi/lo split [b][n][ci]
__device__ __nv_bfloat16 d_th_lo[B_ * N_ * CI_];
__device__ __nv_bfloat16 d_ph_hi[B_ * N_ * CI_];     // phi hi/lo split [b][n][ci]
__device__ __nv_bfloat16 d_ph_lo[B_ * N_ * CI_];
__device__ __nv_bfloat16 d_g_b [B_ * CI_ * N_];      // g bf16, transposed [b][ci][n]

// ============================ helpers ============================
__device__ __forceinline__ uint32_t smem_u32(const void* p) {
    uint32_t a;
    asm("{ .reg .u64 t; cvta.to.shared.u64 t, %1; cvt.u32.u64 %0, t; }" : "=r"(a) : "l"(p));
    return a;
}
__device__ __forceinline__ void mma16816(float* c, const uint32_t* a, const uint32_t* b) {
    asm volatile(
        "mma.sync.aligned.m16n8k16.row.col.f32.bf16.bf16.f32 "
        "{%0,%1,%2,%3}, {%4,%5,%6,%7}, {%8,%9}, {%0,%1,%2,%3};"
        : "+f"(c[0]), "+f"(c[1]), "+f"(c[2]), "+f"(c[3])
        : "r"(a[0]), "r"(a[1]), "r"(a[2]), "r"(a[3]), "r"(b[0]), "r"(b[1]));
}
__device__ __forceinline__ void ldmx4(uint32_t* r, uint32_t addr) {
    asm volatile("ldmatrix.sync.aligned.m8n8.x4.shared.b16 {%0,%1,%2,%3}, [%4];"
                 : "=r"(r[0]), "=r"(r[1]), "=r"(r[2]), "=r"(r[3]) : "r"(addr));
}
__device__ __forceinline__ uint32_t pack_bf16x2(float lo, float hi) {
    uint32_t r;
    asm("cvt.rn.bf16x2.f32 %0, %1, %2;" : "=r"(r) : "f"(hi), "f"(lo));
    return r;
}
__device__ __forceinline__ float bf16_round(float v) {
    return __bfloat162float(__float2bfloat16(v));
}

// ============================ Kernel 1: projections ============================
__global__ __launch_bounds__(256) void proj_kernel(
    const float* __restrict__ x,
    const float* __restrict__ gw, const float* __restrict__ gb,
    const float* __restrict__ tw, const float* __restrict__ tb,
    const float* __restrict__ pw, const float* __restrict__ pb)
{
    const int nt = blockIdx.x;   // n tile (64 cols)
    const int b  = blockIdx.y;
    const int pj = blockIdx.z;   // 0 theta, 1 phi, 2 g

    const float* w;  const float* bias;
    if (pj == 0)      { w = tw; bias = tb; }
    else if (pj == 1) { w = pw; bias = pb; }
    else              { w = gw; bias = gb; }

    __shared__ float xs[64][68];
    __shared__ float ws[64][68];

    const int tid = threadIdx.x;
    const int tx  = tid & 15;
    const int ty  = tid >> 4;

    float acc[4][4];
    #pragma unroll
    for (int i = 0; i < 4; i++)
        #pragma unroll
        for (int j = 0; j < 4; j++) acc[i][j] = 0.f;

    const float* xb = x + (size_t)b * C_ * N_ + nt * 64;

    for (int cc = 0; cc < C_; cc += 64) {
        #pragma unroll
        for (int i = 0; i < 4; i++) {
            int r = ty + i * 16;
            *(float4*)&xs[r][tx * 4] =
                *(const float4*)(xb + (size_t)(cc + r) * N_ + tx * 4);
            *(float4*)&ws[r][tx * 4] =
                *(const float4*)(w + r * C_ + cc + tx * 4);
        }
        __syncthreads();

        #pragma unroll
        for (int k = 0; k < 64; k += 4) {
            float a[4][4], bb[4][4];
            #pragma unroll
            for (int i = 0; i < 4; i++)
                *(float4*)a[i] = *(const float4*)&ws[ty * 4 + i][k];
            #pragma unroll
            for (int kk = 0; kk < 4; kk++)
                *(float4*)bb[kk] = *(const float4*)&xs[k + kk][tx * 4];
            #pragma unroll
            for (int i = 0; i < 4; i++)
                #pragma unroll
                for (int kk = 0; kk < 4; kk++)
                    #pragma unroll
                    for (int j = 0; j < 4; j++)
                        acc[i][j] = fmaf(a[i][kk], bb[kk][j], acc[i][j]);
        }
        __syncthreads();
    }

    float bv[4];
    #pragma unroll
    for (int i = 0; i < 4; i++) bv[i] = bias[ty * 4 + i];

    if (pj == 2) {
        __nv_bfloat16* out = d_g_b + (size_t)b * CI_ * N_;
        #pragma unroll
        for (int i = 0; i < 4; i++) {
            uint2 v;
            v.x = pack_bf16x2(acc[i][0] + bv[i], acc[i][1] + bv[i]);
            v.y = pack_bf16x2(acc[i][2] + bv[i], acc[i][3] + bv[i]);
            *(uint2*)(out + (size_t)(ty * 4 + i) * N_ + nt * 64 + tx * 4) = v;
        }
    } else {
        __nv_bfloat16* ohi = (pj == 0 ? d_th_hi : d_ph_hi) + (size_t)b * N_ * CI_;
        __nv_bfloat16* olo = (pj == 0 ? d_th_lo : d_ph_lo) + (size_t)b * N_ * CI_;
        #pragma unroll
        for (int j = 0; j < 4; j++) {
            float v[4], h[4], l[4];
            #pragma unroll
            for (int i = 0; i < 4; i++) {
                v[i] = acc[i][j] + bv[i];
                h[i] = bf16_round(v[i]);
                l[i] = v[i] - h[i];
            }
            size_t o = (size_t)(nt * 64 + tx * 4 + j) * CI_ + ty * 4;
            uint2 vh, vl;
            vh.x = pack_bf16x2(h[0], h[1]); vh.y = pack_bf16x2(h[2], h[3]);
            vl.x = pack_bf16x2(l[0], l[1]); vl.y = pack_bf16x2(l[2], l[3]);
            *(uint2*)(ohi + o) = vh;
            *(uint2*)(olo + o) = vl;
        }
    }
}

// ============================ Kernel 2: mma.sync flash attention ============================
// CTA: 256 thr / 8 warps, 128 query rows (16 per warp), loop 64 key tiles of 64.
// theta A-frags in registers (hi+lo). phi/g tiles in smem, ldmatrix B-frags.
constexpr int PH_STRIDE = 72;   // bf16 elems per smem row (64 + 8 pad -> conflict-free)

__global__ __launch_bounds__(256, 2) void attn_kernel()
{
    __shared__ __nv_bfloat16 ph_hi[64 * PH_STRIDE];
    __shared__ __nv_bfloat16 ph_lo[64 * PH_STRIDE];
    __shared__ __nv_bfloat16 gs   [64 * PH_STRIDE];

    const int tid = threadIdx.x;
    const int wid = tid >> 5, lane = tid & 31;
    const int nt  = blockIdx.x;   // 128-query tile
    const int b   = blockIdx.y;

    const int lr = lane >> 2;       // 0..7  (row within 8)
    const int lc = lane & 3;        // 0..3  (col pair group)

    // ---- load theta A-fragments (hi & lo) into registers ----
    // warp w owns query rows q0 = nt*128 + w*16 .. +15
    const int q0 = nt * 128 + wid * 16;
    const __nv_bfloat16* thh = d_th_hi + ((size_t)b * N_ + q0) * CI_;
    const __nv_bfloat16* thl = d_th_lo + ((size_t)b * N_ + q0) * CI_;

    uint32_t a_hi[4][4], a_lo[4][4];
    #pragma unroll
    for (int kc = 0; kc < 4; kc++) {
        int c0 = kc * 16 + lc * 2;
        a_hi[kc][0] = *(const uint32_t*)(thh + (size_t)lr * CI_ + c0);
        a_hi[kc][1] = *(const uint32_t*)(thh + (size_t)(lr + 8) * CI_ + c0);
        a_hi[kc][2] = *(const uint32_t*)(thh + (size_t)lr * CI_ + c0 + 8);
        a_hi[kc][3] = *(const uint32_t*)(thh + (size_t)(lr + 8) * CI_ + c0 + 8);
        a_lo[kc][0] = *(const uint32_t*)(thl + (size_t)lr * CI_ + c0);
        a_lo[kc][1] = *(const uint32_t*)(thl + (size_t)(lr + 8) * CI_ + c0);
        a_lo[kc][2] = *(const uint32_t*)(thl + (size_t)lr * CI_ + c0 + 8);
        a_lo[kc][3] = *(const uint32_t*)(thl + (size_t)(lr + 8) * CI_ + c0 + 8);
    }

    const __nv_bfloat16* phh = d_ph_hi + (size_t)b * N_ * CI_;
    const __nv_bfloat16* phl = d_ph_lo + (size_t)b * N_ * CI_;
    const __nv_bfloat16* gbb = d_g_b  + (size_t)b * CI_ * N_;

    // ldmatrix base addresses for this thread (16x16 block pattern):
    // row_in_tile = ((lane>>4)<<3) + (lane&7), col_half = (lane>>3)&1
    const int lmr = ((lane >> 4) << 3) + (lane & 7);
    const int lmc = ((lane >> 3) & 1) * 8;
    const uint32_t ph_hi_b = smem_u32(ph_hi);
    const uint32_t ph_lo_b = smem_u32(ph_lo);
    const uint32_t gs_b    = smem_u32(gs);

    float yacc[8][4];
    #pragma unroll
    for (int i = 0; i < 8; i++)
        #pragma unroll
        for (int j = 0; j < 4; j++) yacc[i][j] = 0.f;
    float rs0 = 0.f, rs1 = 0.f;

    for (int kt = 0; kt < 64; kt++) {
        __syncthreads();   // previous tile's compute done

        // ---- cooperative tile load: phi hi/lo rows [kt*64, +64), g cols same ----
        {
            const __nv_bfloat16* sh = phh + (size_t)kt * 64 * CI_;
            const __nv_bfloat16* sl = phl + (size_t)kt * 64 * CI_;
            #pragma unroll
            for (int i = 0; i < 2; i++) {
                int c16 = tid * 2 + i;             // 0..511
                int row = c16 >> 3, c8 = (c16 & 7) * 8;
                *(uint4*)&ph_hi[row * PH_STRIDE + c8] = *(const uint4*)(sh + row * CI_ + c8);
                *(uint4*)&ph_lo[row * PH_STRIDE + c8] = *(const uint4*)(sl + row * CI_ + c8);
                *(uint4*)&gs   [row * PH_STRIDE + c8] = *(const uint4*)(gbb + (size_t)row * N_ + kt * 64 + c8);
            }
        }
        __syncthreads();

        // ---- S = theta . phi^T  (hi.hi + lo.hi + hi.lo) ----
        float s[8][4];
        #pragma unroll
        for (int i = 0; i < 8; i++)
            #pragma unroll
            for (int j = 0; j < 4; j++) s[i][j] = 0.f;

        #pragma unroll
        for (int kc = 0; kc < 4; kc++) {
            #pragma unroll
            for (int kyg = 0; kyg < 4; kyg++) {   // 16-key groups
                uint32_t bh[4];
                ldmx4(bh, ph_hi_b + ((kyg * 16 + lmr) * PH_STRIDE + kc * 16 + lmc) * 2);
                mma16816(s[2 * kyg],     a_hi[kc], bh);
                mma16816(s[2 * kyg + 1], a_hi[kc], bh + 2);
                mma16816(s[2 * kyg],     a_lo[kc], bh);
                mma16816(s[2 * kyg + 1], a_lo[kc], bh + 2);
            }
        }
        #pragma unroll
        for (int kc = 0; kc < 4; kc++) {
            #pragma unroll
            for (int kyg = 0; kyg < 4; kyg++) {
                uint32_t bl[4];
                ldmx4(bl, ph_lo_b + ((kyg * 16 + lmr) * PH_STRIDE + kc * 16 + lmc) * 2);
                mma16816(s[2 * kyg],     a_hi[kc], bl);
                mma16816(s[2 * kyg + 1], a_hi[kc], bl + 2);
            }
        }

        // ---- exp + rowsum + pack P into A-frags ----
        uint32_t pa[4][4];   // [key chunk kc][a-frag reg]
        #pragma unroll
        for (int i = 0; i < 8; i++) {
            float e0 = __expf(s[i][0]);
            float e1 = __expf(s[i][1]);
            float e2 = __expf(s[i][2]);
            float e3 = __expf(s[i][3]);
            rs0 += e0 + e1;
            rs1 += e2 + e3;
            pa[i >> 1][(i & 1) ? 2 : 0] = pack_bf16x2(e0, e1);
            pa[i >> 1][(i & 1) ? 3 : 1] = pack_bf16x2(e2, e3);
        }

        // ---- Y += P . g ----
        #pragma unroll
        for (int kkc = 0; kkc < 4; kkc++) {       // 16-key chunks
            #pragma unroll
            for (int cg = 0; cg < 4; cg++) {      // 16-ci groups
                uint32_t bg[4];
                ldmx4(bg, gs_b + ((cg * 16 + lmr) * PH_STRIDE + kkc * 16 + lmc) * 2);
                mma16816(yacc[2 * cg],     pa[kkc], bg);
                mma16816(yacc[2 * cg + 1], pa[kkc], bg + 2);
            }
        }
    }

    // full row sums (reduce over the 4 lanes sharing a row)
    rs0 += __shfl_xor_sync(0xFFFFFFFFu, rs0, 1);
    rs0 += __shfl_xor_sync(0xFFFFFFFFu, rs0, 2);
    rs1 += __shfl_xor_sync(0xFFFFFFFFu, rs1, 1);
    rs1 += __shfl_xor_sync(0xFFFFFFFFu, rs1, 2);
    const float i0 = 1.f / rs0, i1 = 1.f / rs1;

    // store Y [q][ci]
    float* yp = d_y + ((size_t)b * N_ + q0) * CI_;
    #pragma unroll
    for (int nf = 0; nf < 8; nf++) {
        int c = nf * 8 + lc * 2;
        *(float2*)(yp + (size_t)lr * CI_ + c) =
            make_float2(yacc[nf][0] * i0, yacc[nf][1] * i0);
        *(float2*)(yp + (size_t)(lr + 8) * CI_ + c) =
            make_float2(yacc[nf][2] * i1, yacc[nf][3] * i1);
    }
}

// ============================ Kernel 3: output conv + residual ============================
__global__ __launch_bounds__(256) void wconv_kernel(
    const float* __restrict__ x,
    const float* __restrict__ ww, const float* __restrict__ wb,
    float* __restrict__ out)
{
    const int nt = blockIdx.x;
    const int ct = blockIdx.y;
    const int b  = blockIdx.z;

    __shared__ float ys[32][68];
    __shared__ float ws[128][68];

    const int tid = threadIdx.x;
    {
        const int lx = tid & 15, ln = tid >> 4;
        const float* yb = d_y + ((size_t)b * N_ + nt * 32) * CI_;
        #pragma unroll
        for (int i = 0; i < 2; i++) {
            int n = ln + i * 16;
            *(float4*)&ys[n][lx * 4] = *(const float4*)(yb + (size_t)n * CI_ + lx * 4);
        }
        #pragma unroll
        for (int i = 0; i < 8; i++) {
            int co = ln + i * 16;
            *(float4*)&ws[co][lx * 4] =
                *(const float4*)(ww + (size_t)(ct * 128 + co) * CI_ + lx * 4);
        }
    }
    __syncthreads();

    const int tx = tid & 7;
    const int ty = tid >> 3;

    float acc[4][4];
    #pragma unroll
    for (int i = 0; i < 4; i++)
        #pragma unroll
        for (int j = 0; j < 4; j++) acc[i][j] = 0.f;

    #pragma unroll
    for (int k = 0; k < 64; k += 4) {
        float a[4][4], yv[4][4];
        #pragma unroll
        for (int i = 0; i < 4; i++)
            *(float4*)a[i] = *(const float4*)&ws[ty * 4 + i][k];
        #pragma unroll
        for (int j = 0; j < 4; j++)
            *(float4*)yv[j] = *(const float4*)&ys[tx * 4 + j][k];
        #pragma unroll
        for (int i = 0; i < 4; i++)
            #pragma unroll
            for (int j = 0; j < 4; j++)
                #pragma unroll
                for (int kk = 0; kk < 4; kk++)
                    acc[i][j] = fmaf(a[i][kk], yv[j][kk], acc[i][j]);
    }

    #pragma unroll
    for (int i = 0; i < 4; i++) {
        int co = ct * 128 + ty * 4 + i;
        float bv = wb[co];
        size_t base = ((size_t)b * C_ + co) * N_ + nt * 32 + tx * 4;
        float4 xv = *(const float4*)(x + base);
        float4 v = make_float4(acc[i][0] + bv + xv.x, acc[i][1] + bv + xv.y,
                               acc[i][2] + bv + xv.z, acc[i][3] + bv + xv.w);
        *(float4*)(out + base) = v;
    }
}

// ---------------------------------------------------------------------------
extern "C" void kernel_launch(void* const* d_in, const int* in_sizes, int n_in,
                              void* d_out, int out_size)
{
    const float* x  = (const float*)d_in[0];
    const float* gw = (const float*)d_in[1];
    const float* gb = (const float*)d_in[2];
    const float* tw = (const float*)d_in[3];
    const float* tb = (const float*)d_in[4];
    const float* pw = (const float*)d_in[5];
    const float* pb = (const float*)d_in[6];
    const float* ww = (const float*)d_in[7];
    const float* wb = (const float*)d_in[8];
    float* out = (float*)d_out;

    proj_kernel<<<dim3(N_ / 64, B_, 3), 256>>>(x, gw, gb, tw, tb, pw, pb);
    attn_kernel<<<dim3(N_ / 128, B_), 256>>>();
    wconv_kernel<<<dim3(N_ / 32, 2, B_), 256>>>(x, ww, wb, out);
}

// round 5
// speedup vs baseline: 2.9348x; 1.4479x over previous
#include <cuda_runtime.h>
#include <cuda_bf16.h>
#include <cstdint>

// Problem constants
constexpr int B_  = 8;
constexpr int C_  = 256;
constexpr int CI_ = 64;
constexpr int N_  = 4096;   // H*W

// ---------------- scratch (device globals: allocation-free rule) ----------------
__device__ __nv_bfloat16 d_x_hi[B_ * C_ * N_];   // x split, [b][c][n]
__device__ __nv_bfloat16 d_x_lo[B_ * C_ * N_];
__device__ __nv_bfloat16 d_w_hi[3 * CI_ * C_];   // proj weights split: theta, phi, g
__device__ __nv_bfloat16 d_w_lo[3 * CI_ * C_];
__device__ __nv_bfloat16 d_w2_hi[C_ * CI_];      // output conv weight split [co][ci]
__device__ __nv_bfloat16 d_w2_lo[C_ * CI_];
__device__ __nv_bfloat16 d_th_hi[B_ * CI_ * N_]; // theta [b][ci][n]
__device__ __nv_bfloat16 d_th_lo[B_ * CI_ * N_];
__device__ __nv_bfloat16 d_ph_hi[B_ * CI_ * N_]; // phi [b][ci][n]
__device__ __nv_bfloat16 d_ph_lo[B_ * CI_ * N_];
__device__ __nv_bfloat16 d_g   [B_ * CI_ * N_];  // g bf16 [b][ci][n]
__device__ __nv_bfloat16 d_y_hi[B_ * N_ * CI_];  // attention out split [b][n][ci]
__device__ __nv_bfloat16 d_y_lo[B_ * N_ * CI_];

// ---------------- helpers ----------------
__device__ __forceinline__ uint32_t smem_u32(const void* p) {
    uint32_t a;
    asm("{ .reg .u64 t; cvta.to.shared.u64 t, %1; cvt.u32.u64 %0, t; }" : "=r"(a) : "l"(p));
    return a;
}
__device__ __forceinline__ void mma16816(float* c, const uint32_t* a, const uint32_t* b) {
    asm volatile(
        "mma.sync.aligned.m16n8k16.row.col.f32.bf16.bf16.f32 "
        "{%0,%1,%2,%3}, {%4,%5,%6,%7}, {%8,%9}, {%0,%1,%2,%3};"
        : "+f"(c[0]), "+f"(c[1]), "+f"(c[2]), "+f"(c[3])
        : "r"(a[0]), "r"(a[1]), "r"(a[2]), "r"(a[3]), "r"(b[0]), "r"(b[1]));
}
__device__ __forceinline__ void ldmx4(uint32_t* r, uint32_t addr) {
    asm volatile("ldmatrix.sync.aligned.m8n8.x4.shared.b16 {%0,%1,%2,%3}, [%4];"
                 : "=r"(r[0]), "=r"(r[1]), "=r"(r[2]), "=r"(r[3]) : "r"(addr));
}
__device__ __forceinline__ void ldmx4t(uint32_t* r, uint32_t addr) {
    asm volatile("ldmatrix.sync.aligned.m8n8.x4.trans.shared.b16 {%0,%1,%2,%3}, [%4];"
                 : "=r"(r[0]), "=r"(r[1]), "=r"(r[2]), "=r"(r[3]) : "r"(addr));
}
__device__ __forceinline__ uint32_t pack_bf16x2(float lo, float hi) {
    uint32_t r;
    asm("cvt.rn.bf16x2.f32 %0, %1, %2;" : "=r"(r) : "f"(hi), "f"(lo));
    return r;
}
__device__ __forceinline__ float bf16_round(float v) {
    return __bfloat162float(__float2bfloat16(v));
}
__device__ __forceinline__ void cp16(uint32_t s, const void* g) {
    asm volatile("cp.async.cg.shared.global [%0], [%1], 16;" :: "r"(s), "l"(g));
}
__device__ __forceinline__ void cp_commit() { asm volatile("cp.async.commit_group;"); }
template <int n> __device__ __forceinline__ void cp_wait() {
    asm volatile("cp.async.wait_group %0;" :: "n"(n));
}

// ============== Kernel 0a: split x into bf16 hi/lo ==============
__global__ __launch_bounds__(512) void split_x_kernel(const float* __restrict__ x)
{
    int i = blockIdx.x * 512 + threadIdx.x;      // float4 index, 2097152 total
    float4 v = ((const float4*)x)[i];
    float h0 = bf16_round(v.x), h1 = bf16_round(v.y);
    float h2 = bf16_round(v.z), h3 = bf16_round(v.w);
    uint2 hi, lo;
    hi.x = pack_bf16x2(h0, h1); hi.y = pack_bf16x2(h2, h3);
    lo.x = pack_bf16x2(v.x - h0, v.y - h1);
    lo.y = pack_bf16x2(v.z - h2, v.w - h3);
    ((uint2*)d_x_hi)[i] = hi;
    ((uint2*)d_x_lo)[i] = lo;
}

// ============== Kernel 0b: split weights ==============
__global__ __launch_bounds__(256) void split_w_kernel(
    const float* __restrict__ tw, const float* __restrict__ pw,
    const float* __restrict__ gw, const float* __restrict__ w2)
{
    int i = blockIdx.x * 256 + threadIdx.x;      // 0..16383
    float v, h;
    v = tw[i]; h = bf16_round(v);
    d_w_hi[i] = __float2bfloat16(h); d_w_lo[i] = __float2bfloat16(v - h);
    v = pw[i]; h = bf16_round(v);
    d_w_hi[16384 + i] = __float2bfloat16(h); d_w_lo[16384 + i] = __float2bfloat16(v - h);
    v = gw[i]; h = bf16_round(v);
    d_w_hi[32768 + i] = __float2bfloat16(h); d_w_lo[32768 + i] = __float2bfloat16(v - h);
    v = w2[i]; h = bf16_round(v);
    d_w2_hi[i] = __float2bfloat16(h); d_w2_lo[i] = __float2bfloat16(v - h);
}

// ============== Kernel 1: projections via mma.sync ==============
// CTA: 256 thr, n-tile 128, one projection. M=64(ci), N=128, K=256 in 2 chunks of 128.
// smem: ws_hi[64][136], ws_lo, xs_hi[128][136], xs_lo (strides in elems; 272B rows)
constexpr int PJ_WS_HI = 0;
constexpr int PJ_WS_LO = 17408;
constexpr int PJ_XS_HI = 34816;
constexpr int PJ_XS_LO = 69632;
constexpr int PJ_SMEM  = 104448;

__global__ __launch_bounds__(256) void proj_kernel(
    const float* __restrict__ tb, const float* __restrict__ pb,
    const float* __restrict__ gb)
{
    extern __shared__ char sm[];
    const uint32_t sb = smem_u32(sm);
    const int tid = threadIdx.x;
    const int wid = tid >> 5, lane = tid & 31;
    const int nt = blockIdx.x, b = blockIdx.y, pj = blockIdx.z;
    const int lr = lane >> 2, lc = lane & 3;

    const __nv_bfloat16* wh = d_w_hi + pj * CI_ * C_;
    const __nv_bfloat16* wl = d_w_lo + pj * CI_ * C_;
    const __nv_bfloat16* xh = d_x_hi + (size_t)b * C_ * N_ + nt * 128;
    const __nv_bfloat16* xl = d_x_lo + (size_t)b * C_ * N_ + nt * 128;

    const int mi = wid & 3, nh = wid >> 2;
    // lane maps
    const int amr = (lane & 7) + ((lane >> 3) & 1) * 8;   // A non-trans m-offset
    const int akc = (lane >> 4) * 8;                       // A non-trans k-offset
    const int bkr = ((lane >> 3) & 1) * 8 + (lane & 7);    // B trans k(row)-offset
    const int bnc = (lane >> 4) * 8;                       // B trans n(col)-offset

    float acc[8][4];
    #pragma unroll
    for (int i = 0; i < 8; i++)
        #pragma unroll
        for (int j = 0; j < 4; j++) acc[i][j] = 0.f;

    for (int ch = 0; ch < 2; ch++) {
        __syncthreads();
        // load w chunk [64 ci][128 c]  (256B/row -> 16 chunks of 16B, 1024 total)
        #pragma unroll
        for (int j = 0; j < 4; j++) {
            int idx = tid + j * 256;            // 0..1023
            int row = idx >> 4, c16 = idx & 15;
            uint32_t so = row * 272 + c16 * 16;
            size_t go = (size_t)row * C_ + ch * 128 + c16 * 8;
            *(uint4*)(sm + PJ_WS_HI + so) = *(const uint4*)(wh + go);
            *(uint4*)(sm + PJ_WS_LO + so) = *(const uint4*)(wl + go);
        }
        // load x chunk [128 c][128 n]
        #pragma unroll
        for (int j = 0; j < 8; j++) {
            int idx = tid + j * 256;            // 0..2047
            int row = idx >> 4, c16 = idx & 15;
            uint32_t so = row * 272 + c16 * 16;
            size_t go = (size_t)(ch * 128 + row) * N_ + c16 * 8;
            *(uint4*)(sm + PJ_XS_HI + so) = *(const uint4*)(xh + go);
            *(uint4*)(sm + PJ_XS_LO + so) = *(const uint4*)(xl + go);
        }
        __syncthreads();

        #pragma unroll
        for (int ks = 0; ks < 8; ks++) {
            uint32_t a_hi[4], a_lo[4];
            uint32_t ao = ((mi * 16 + amr) * 136 + ks * 16 + akc) * 2;
            ldmx4(a_hi, sb + PJ_WS_HI + ao);
            ldmx4(a_lo, sb + PJ_WS_LO + ao);
            #pragma unroll
            for (int nf4 = 0; nf4 < 4; nf4++) {
                uint32_t bo = ((ks * 16 + bkr) * 136 + nh * 64 + nf4 * 16 + bnc) * 2;
                uint32_t bh[4], bl[4];
                ldmx4t(bh, sb + PJ_XS_HI + bo);
                mma16816(acc[2 * nf4],     a_hi, bh);
                mma16816(acc[2 * nf4 + 1], a_hi, bh + 2);
                mma16816(acc[2 * nf4],     a_lo, bh);
                mma16816(acc[2 * nf4 + 1], a_lo, bh + 2);
                ldmx4t(bl, sb + PJ_XS_LO + bo);
                mma16816(acc[2 * nf4],     a_hi, bl);
                mma16816(acc[2 * nf4 + 1], a_hi, bl + 2);
            }
        }
    }

    const float* bias = (pj == 0) ? tb : (pj == 1) ? pb : gb;
    const int ci0 = mi * 16 + lr;
    const float bv0 = bias[ci0], bv1 = bias[ci0 + 8];

    if (pj == 2) {
        __nv_bfloat16* out = d_g + (size_t)b * CI_ * N_;
        #pragma unroll
        for (int nf = 0; nf < 8; nf++) {
            size_t n = (size_t)nt * 128 + nh * 64 + nf * 8 + lc * 2;
            *(uint32_t*)(out + (size_t)ci0 * N_ + n) =
                pack_bf16x2(acc[nf][0] + bv0, acc[nf][1] + bv0);
            *(uint32_t*)(out + (size_t)(ci0 + 8) * N_ + n) =
                pack_bf16x2(acc[nf][2] + bv1, acc[nf][3] + bv1);
        }
    } else {
        __nv_bfloat16* ohi = (pj == 0 ? d_th_hi : d_ph_hi) + (size_t)b * CI_ * N_;
        __nv_bfloat16* olo = (pj == 0 ? d_th_lo : d_ph_lo) + (size_t)b * CI_ * N_;
        #pragma unroll
        for (int nf = 0; nf < 8; nf++) {
            size_t n = (size_t)nt * 128 + nh * 64 + nf * 8 + lc * 2;
            float v0 = acc[nf][0] + bv0, v1 = acc[nf][1] + bv0;
            float v2 = acc[nf][2] + bv1, v3 = acc[nf][3] + bv1;
            float h0 = bf16_round(v0), h1 = bf16_round(v1);
            float h2 = bf16_round(v2), h3 = bf16_round(v3);
            *(uint32_t*)(ohi + (size_t)ci0 * N_ + n)       = pack_bf16x2(h0, h1);
            *(uint32_t*)(olo + (size_t)ci0 * N_ + n)       = pack_bf16x2(v0 - h0, v1 - h1);
            *(uint32_t*)(ohi + (size_t)(ci0 + 8) * N_ + n) = pack_bf16x2(h2, h3);
            *(uint32_t*)(olo + (size_t)(ci0 + 8) * N_ + n) = pack_bf16x2(v2 - h2, v3 - h3);
        }
    }
}

// ============== Kernel 2: flash attention, cp.async 3-stage pipeline ==============
// CTA 256 thr / 8 warps, 128 queries (16/warp), 64 key tiles of 64.
// Stage: ph_hi[64ci][64k] + ph_lo + gs, each 64 rows x 144B (stride 72 elems).
constexpr int AT_TILE  = 9216;       // 64*144
constexpr int AT_STAGE = 27648;      // 3 tiles
constexpr int AT_SMEM  = 82944;      // 3 stages

__device__ __forceinline__ void attn_stage_issue(
    uint32_t sbase, const __nv_bfloat16* phh, const __nv_bfloat16* phl,
    const __nv_bfloat16* gg, int kt, int tid)
{
    const __nv_bfloat16* src[3] = { phh, phl, gg };
    #pragma unroll
    for (int t3 = 0; t3 < 3; t3++) {
        #pragma unroll
        for (int j = 0; j < 2; j++) {
            int idx = tid + j * 256;             // 0..511
            int row = idx >> 3, c16 = idx & 7;
            cp16(sbase + t3 * AT_TILE + row * 144 + c16 * 16,
                 src[t3] + (size_t)row * N_ + kt * 64 + c16 * 8);
        }
    }
}

__global__ __launch_bounds__(256, 2) void attn_kernel()
{
    extern __shared__ char sm[];
    const uint32_t sb = smem_u32(sm);
    const int tid = threadIdx.x;
    const int wid = tid >> 5, lane = tid & 31;
    const int nt = blockIdx.x, b = blockIdx.y;
    const int lr = lane >> 2, lc = lane & 3;

    const __nv_bfloat16* phh = d_ph_hi + (size_t)b * CI_ * N_;
    const __nv_bfloat16* phl = d_ph_lo + (size_t)b * CI_ * N_;
    const __nv_bfloat16* gg  = d_g    + (size_t)b * CI_ * N_;
    const __nv_bfloat16* thh = d_th_hi + (size_t)b * CI_ * N_ + nt * 128;
    const __nv_bfloat16* thl = d_th_lo + (size_t)b * CI_ * N_ + nt * 128;

    // prefetch stages 0 and 1
    attn_stage_issue(sb, phh, phl, gg, 0, tid); cp_commit();
    attn_stage_issue(sb + AT_STAGE, phh, phl, gg, 1, tid); cp_commit();

    // theta A-frags via trans ldmatrix, staged through stage-2 region (reused later)
    const uint32_t th_region = sb + 2 * AT_STAGE;
    const int tkr = (lane >> 4) * 8 + (lane & 7);      // A trans k(row)-offset
    const int tmc = ((lane >> 3) & 1) * 8;             // A trans m(col)-offset
    uint32_t a_hi[4][4], a_lo[4][4];
    {
        // theta_hi tile [64 ci][128 q], stride 136 elems
        #pragma unroll
        for (int j = 0; j < 4; j++) {
            int idx = tid + j * 256;                   // 0..1023
            int row = idx >> 4, c16 = idx & 15;
            *(uint4*)(sm + 2 * AT_STAGE + row * 272 + c16 * 16) =
                *(const uint4*)(thh + (size_t)row * N_ + c16 * 8);
        }
        __syncthreads();
        #pragma unroll
        for (int kc = 0; kc < 4; kc++)
            ldmx4t(a_hi[kc], th_region + ((kc * 16 + tkr) * 136 + wid * 16 + tmc) * 2);
        __syncthreads();
        #pragma unroll
        for (int j = 0; j < 4; j++) {
            int idx = tid + j * 256;
            int row = idx >> 4, c16 = idx & 15;
            *(uint4*)(sm + 2 * AT_STAGE + row * 272 + c16 * 16) =
                *(const uint4*)(thl + (size_t)row * N_ + c16 * 8);
        }
        __syncthreads();
        #pragma unroll
        for (int kc = 0; kc < 4; kc++)
            ldmx4t(a_lo[kc], th_region + ((kc * 16 + tkr) * 136 + wid * 16 + tmc) * 2);
    }

    // lane maps for B frags
    const int bkr = ((lane >> 3) & 1) * 8 + (lane & 7);   // trans (phi)
    const int bnc = (lane >> 4) * 8;
    const int lmr = ((lane >> 4) << 3) + (lane & 7);      // non-trans (g)
    const int lmc = ((lane >> 3) & 1) * 8;

    float yacc[8][4];
    #pragma unroll
    for (int i = 0; i < 8; i++)
        #pragma unroll
        for (int j = 0; j < 4; j++) yacc[i][j] = 0.f;
    float rs0 = 0.f, rs1 = 0.f;

    for (int kt = 0; kt < 64; kt++) {
        cp_wait<1>();
        __syncthreads();
        // prefetch kt+2 (buffer (kt+2)%3 was released by the barrier above)
        if (kt + 2 < 64)
            attn_stage_issue(sb + ((kt + 2) % 3) * AT_STAGE, phh, phl, gg, kt + 2, tid);
        cp_commit();   // always commit (possibly empty) to keep group count uniform

        const uint32_t SB = sb + (kt % 3) * AT_STAGE;

        // ---- S = theta . phi^T (hi.hi + lo.hi + hi.lo) ----
        float s[8][4];
        #pragma unroll
        for (int i = 0; i < 8; i++)
            #pragma unroll
            for (int j = 0; j < 4; j++) s[i][j] = 0.f;

        #pragma unroll
        for (int kc = 0; kc < 4; kc++) {
            #pragma unroll
            for (int kyg = 0; kyg < 4; kyg++) {
                uint32_t bo = ((kc * 16 + bkr) * 72 + kyg * 16 + bnc) * 2;
                uint32_t bh[4], bl[4];
                ldmx4t(bh, SB + bo);                       // ph_hi at tile offset 0
                mma16816(s[2 * kyg],     a_hi[kc], bh);
                mma16816(s[2 * kyg + 1], a_hi[kc], bh + 2);
                mma16816(s[2 * kyg],     a_lo[kc], bh);
                mma16816(s[2 * kyg + 1], a_lo[kc], bh + 2);
                ldmx4t(bl, SB + AT_TILE + bo);             // ph_lo
                mma16816(s[2 * kyg],     a_hi[kc], bl);
                mma16816(s[2 * kyg + 1], a_hi[kc], bl + 2);
            }
        }

        // ---- exp + rowsum + pack P ----
        uint32_t pa[4][4];
        #pragma unroll
        for (int i = 0; i < 8; i++) {
            float e0 = __expf(s[i][0]);
            float e1 = __expf(s[i][1]);
            float e2 = __expf(s[i][2]);
            float e3 = __expf(s[i][3]);
            rs0 += e0 + e1;
            rs1 += e2 + e3;
            pa[i >> 1][(i & 1) ? 2 : 0] = pack_bf16x2(e0, e1);
            pa[i >> 1][(i & 1) ? 3 : 1] = pack_bf16x2(e2, e3);
        }

        // ---- Y += P . g ----
        #pragma unroll
        for (int kkc = 0; kkc < 4; kkc++) {
            #pragma unroll
            for (int cg = 0; cg < 4; cg++) {
                uint32_t bg[4];
                ldmx4(bg, SB + 2 * AT_TILE + ((cg * 16 + lmr) * 72 + kkc * 16 + lmc) * 2);
                mma16816(yacc[2 * cg],     pa[kkc], bg);
                mma16816(yacc[2 * cg + 1], pa[kkc], bg + 2);
            }
        }
    }

    rs0 += __shfl_xor_sync(0xFFFFFFFFu, rs0, 1);
    rs0 += __shfl_xor_sync(0xFFFFFFFFu, rs0, 2);
    rs1 += __shfl_xor_sync(0xFFFFFFFFu, rs1, 1);
    rs1 += __shfl_xor_sync(0xFFFFFFFFu, rs1, 2);
    const float i0 = 1.f / rs0, i1 = 1.f / rs1;

    // store y hi/lo [b][n][ci]
    const int q0 = nt * 128 + wid * 16;
    __nv_bfloat16* yh = d_y_hi + ((size_t)b * N_ + q0) * CI_;
    __nv_bfloat16* yl = d_y_lo + ((size_t)b * N_ + q0) * CI_;
    #pragma unroll
    for (int nf = 0; nf < 8; nf++) {
        int c = nf * 8 + lc * 2;
        float v0 = yacc[nf][0] * i0, v1 = yacc[nf][1] * i0;
        float v2 = yacc[nf][2] * i1, v3 = yacc[nf][3] * i1;
        float h0 = bf16_round(v0), h1 = bf16_round(v1);
        float h2 = bf16_round(v2), h3 = bf16_round(v3);
        *(uint32_t*)(yh + (size_t)lr * CI_ + c)       = pack_bf16x2(h0, h1);
        *(uint32_t*)(yl + (size_t)lr * CI_ + c)       = pack_bf16x2(v0 - h0, v1 - h1);
        *(uint32_t*)(yh + (size_t)(lr + 8) * CI_ + c) = pack_bf16x2(h2, h3);
        *(uint32_t*)(yl + (size_t)(lr + 8) * CI_ + c) = pack_bf16x2(v2 - h2, v3 - h3);
    }
}

// ============== Kernel 3: output conv + residual via mma.sync ==============
// grid (32 n-tiles of 128, 2 co-halves of 128, B). 256 thr.
constexpr int WC_W_HI = 0;       // [128 co][64 ci] stride 72
constexpr int WC_W_LO = 18432;
constexpr int WC_Y_HI = 36864;   // [128 n][64 ci] stride 72
constexpr int WC_Y_LO = 55296;
constexpr int WC_SMEM = 73728;

__global__ __launch_bounds__(256) void wconv_kernel(
    const float* __restrict__ x, const float* __restrict__ wb,
    float* __restrict__ out)
{
    extern __shared__ char sm[];
    const uint32_t sb = smem_u32(sm);
    const int tid = threadIdx.x;
    const int wid = tid >> 5, lane = tid & 31;
    const int nt = blockIdx.x, ct = blockIdx.y, b = blockIdx.z;
    const int lr = lane >> 2, lc = lane & 3;

    // loads
    #pragma unroll
    for (int j = 0; j < 4; j++) {
        int idx = tid + j * 256;          // 0..1023
        int row = idx >> 3, c16 = idx & 7;
        uint32_t so = row * 144 + c16 * 16;
        size_t gw = (size_t)(ct * 128 + row) * CI_ + c16 * 8;
        *(uint4*)(sm + WC_W_HI + so) = *(const uint4*)(d_w2_hi + gw);
        *(uint4*)(sm + WC_W_LO + so) = *(const uint4*)(d_w2_lo + gw);
        size_t gy = ((size_t)b * N_ + nt * 128 + row) * CI_ + c16 * 8;
        *(uint4*)(sm + WC_Y_HI + so) = *(const uint4*)(d_y_hi + gy);
        *(uint4*)(sm + WC_Y_LO + so) = *(const uint4*)(d_y_lo + gy);
    }
    __syncthreads();

    const int mi = wid & 3, nh = wid >> 2;
    const int amr = (lane & 7) + ((lane >> 3) & 1) * 8;
    const int akc = (lane >> 4) * 8;
    const int lmr = ((lane >> 4) << 3) + (lane & 7);
    const int lmc = ((lane >> 3) & 1) * 8;

    float acc[2][8][4];
    #pragma unroll
    for (int m = 0; m < 2; m++)
        #pragma unroll
        for (int i = 0; i < 8; i++)
            #pragma unroll
            for (int j = 0; j < 4; j++) acc[m][i][j] = 0.f;

    #pragma unroll
    for (int ks = 0; ks < 4; ks++) {
        uint32_t ah[2][4], al[2][4];
        #pragma unroll
        for (int m = 0; m < 2; m++) {
            uint32_t ao = ((mi * 32 + m * 16 + amr) * 72 + ks * 16 + akc) * 2;
            ldmx4(ah[m], sb + WC_W_HI + ao);
            ldmx4(al[m], sb + WC_W_LO + ao);
        }
        #pragma unroll
        for (int nf4 = 0; nf4 < 4; nf4++) {
            uint32_t bo = ((nh * 64 + nf4 * 16 + lmr) * 72 + ks * 16 + lmc) * 2;
            uint32_t bh[4], bl[4];
            ldmx4(bh, sb + WC_Y_HI + bo);
            ldmx4(bl, sb + WC_Y_LO + bo);
            #pragma unroll
            for (int m = 0; m < 2; m++) {
                mma16816(acc[m][2 * nf4],     ah[m], bh);
                mma16816(acc[m][2 * nf4 + 1], ah[m], bh + 2);
                mma16816(acc[m][2 * nf4],     al[m], bh);
                mma16816(acc[m][2 * nf4 + 1], al[m], bh + 2);
                mma16816(acc[m][2 * nf4],     ah[m], bl);
                mma16816(acc[m][2 * nf4 + 1], ah[m], bl + 2);
            }
        }
    }

    #pragma unroll
    for (int m = 0; m < 2; m++) {
        int co0 = ct * 128 + mi * 32 + m * 16 + lr;
        float bv0 = wb[co0], bv1 = wb[co0 + 8];
        #pragma unroll
        for (int nf = 0; nf < 8; nf++) {
            size_t n = (size_t)nt * 128 + nh * 64 + nf * 8 + lc * 2;
            size_t base0 = ((size_t)b * C_ + co0) * N_ + n;
            size_t base1 = ((size_t)b * C_ + co0 + 8) * N_ + n;
            float2 x0 = *(const float2*)(x + base0);
            float2 x1 = *(const float2*)(x + base1);
            *(float2*)(out + base0) =
                make_float2(acc[m][nf][0] + bv0 + x0.x, acc[m][nf][1] + bv0 + x0.y);
            *(float2*)(out + base1) =
                make_float2(acc[m][nf][2] + bv1 + x1.x, acc[m][nf][3] + bv1 + x1.y);
        }
    }
}

// ---------------------------------------------------------------------------
extern "C" void kernel_launch(void* const* d_in, const int* in_sizes, int n_in,
                              void* d_out, int out_size)
{
    const float* x  = (const float*)d_in[0];
    const float* gw = (const float*)d_in[1];
    const float* gb = (const float*)d_in[2];
    const float* tw = (const float*)d_in[3];
    const float* tb = (const float*)d_in[4];
    const float* pw = (const float*)d_in[5];
    const float* pb = (const float*)d_in[6];
    const float* ww = (const float*)d_in[7];
    const float* wb = (const float*)d_in[8];
    float* out = (float*)d_out;

    cudaFuncSetAttribute(proj_kernel,  cudaFuncAttributeMaxDynamicSharedMemorySize, PJ_SMEM);
    cudaFuncSetAttribute(attn_kernel,  cudaFuncAttributeMaxDynamicSharedMemorySize, AT_SMEM);
    cudaFuncSetAttribute(wconv_kernel, cudaFuncAttributeMaxDynamicSharedMemorySize, WC_SMEM);

    split_x_kernel<<<4096, 512>>>(x);
    split_w_kernel<<<64, 256>>>(tw, pw, gw, ww);
    proj_kernel<<<dim3(N_ / 128, B_, 3), 256, PJ_SMEM>>>(tb, pb, gb);
    attn_kernel<<<dim3(N_ / 128, B_), 256, AT_SMEM>>>();
    wconv_kernel<<<dim3(N_ / 128, 2, B_), 256, WC_SMEM>>>(x, wb, out);
}

// round 6
// speedup vs baseline: 5.2163x; 1.7774x over previous
#include <cuda_runtime.h>
#include <cuda_bf16.h>
#include <cuda_fp16.h>
#include <cstdint>

// Problem constants
constexpr int B_  = 8;
constexpr int C_  = 256;
constexpr int CI_ = 64;
constexpr int N_  = 4096;   // H*W
constexpr float LOG2E = 1.4426950408889634f;

// ---------------- scratch (device globals: allocation-free rule) ----------------
__device__ __half d_x_h [B_ * C_ * N_];   // x fp16 [b][c][n]
__device__ __half d_w_h [3 * CI_ * C_];   // proj weights fp16: theta, phi, g
__device__ __half d_w2_h[C_ * CI_];       // output conv weight fp16 [co][ci]
__device__ __half d_th  [B_ * CI_ * N_];  // theta fp16 (pre-scaled by log2e) [b][ci][n]
__device__ __half d_ph  [B_ * CI_ * N_];  // phi fp16 [b][ci][n]
__device__ __nv_bfloat16 d_g[B_ * CI_ * N_];  // g bf16 [b][ci][n]
__device__ __half d_y   [B_ * N_ * CI_];  // attention out fp16 [b][n][ci]

// ---------------- helpers ----------------
__device__ __forceinline__ uint32_t smem_u32(const void* p) {
    uint32_t a;
    asm("{ .reg .u64 t; cvta.to.shared.u64 t, %1; cvt.u32.u64 %0, t; }" : "=r"(a) : "l"(p));
    return a;
}
// bf16 mma (used for Y += P.g)
__device__ __forceinline__ void mma_bf16(float* c, const uint32_t* a, const uint32_t* b) {
    asm volatile(
        "mma.sync.aligned.m16n8k16.row.col.f32.bf16.bf16.f32 "
        "{%0,%1,%2,%3}, {%4,%5,%6,%7}, {%8,%9}, {%0,%1,%2,%3};"
        : "+f"(c[0]), "+f"(c[1]), "+f"(c[2]), "+f"(c[3])
        : "r"(a[0]), "r"(a[1]), "r"(a[2]), "r"(a[3]), "r"(b[0]), "r"(b[1]));
}
// fp16 mma with fp32 accum (S, proj, wconv)
__device__ __forceinline__ void mma_f16(float* c, const uint32_t* a, const uint32_t* b) {
    asm volatile(
        "mma.sync.aligned.m16n8k16.row.col.f32.f16.f16.f32 "
        "{%0,%1,%2,%3}, {%4,%5,%6,%7}, {%8,%9}, {%0,%1,%2,%3};"
        : "+f"(c[0]), "+f"(c[1]), "+f"(c[2]), "+f"(c[3])
        : "r"(a[0]), "r"(a[1]), "r"(a[2]), "r"(a[3]), "r"(b[0]), "r"(b[1]));
}
__device__ __forceinline__ void ldmx4(uint32_t* r, uint32_t addr) {
    asm volatile("ldmatrix.sync.aligned.m8n8.x4.shared.b16 {%0,%1,%2,%3}, [%4];"
                 : "=r"(r[0]), "=r"(r[1]), "=r"(r[2]), "=r"(r[3]) : "r"(addr));
}
__device__ __forceinline__ void ldmx4t(uint32_t* r, uint32_t addr) {
    asm volatile("ldmatrix.sync.aligned.m8n8.x4.trans.shared.b16 {%0,%1,%2,%3}, [%4];"
                 : "=r"(r[0]), "=r"(r[1]), "=r"(r[2]), "=r"(r[3]) : "r"(addr));
}
__device__ __forceinline__ uint32_t pack_bf16x2(float lo, float hi) {
    uint32_t r;
    asm("cvt.rn.bf16x2.f32 %0, %1, %2;" : "=r"(r) : "f"(hi), "f"(lo));
    return r;
}
__device__ __forceinline__ uint32_t pack_f16x2(float lo, float hi) {
    uint32_t r;
    asm("cvt.rn.f16x2.f32 %0, %1, %2;" : "=r"(r) : "f"(hi), "f"(lo));
    return r;
}
__device__ __forceinline__ float ex2f(float x) {
    float r;
    asm("ex2.approx.ftz.f32 %0, %1;" : "=f"(r) : "f"(x));
    return r;
}
__device__ __forceinline__ void cp16(uint32_t s, const void* g) {
    asm volatile("cp.async.cg.shared.global [%0], [%1], 16;" :: "r"(s), "l"(g));
}
__device__ __forceinline__ void cp_commit() { asm volatile("cp.async.commit_group;"); }
template <int n> __device__ __forceinline__ void cp_wait() {
    asm volatile("cp.async.wait_group %0;" :: "n"(n));
}

// ============== Kernel 0a: x -> fp16 ==============
__global__ __launch_bounds__(512) void split_x_kernel(const float* __restrict__ x)
{
    int i = blockIdx.x * 512 + threadIdx.x;      // float4 index, 2097152 total
    float4 v = ((const float4*)x)[i];
    uint2 o;
    o.x = pack_f16x2(v.x, v.y);
    o.y = pack_f16x2(v.z, v.w);
    ((uint2*)d_x_h)[i] = o;
}

// ============== Kernel 0b: weights -> fp16 ==============
__global__ __launch_bounds__(256) void split_w_kernel(
    const float* __restrict__ tw, const float* __restrict__ pw,
    const float* __restrict__ gw, const float* __restrict__ w2)
{
    int i = blockIdx.x * 256 + threadIdx.x;      // 0..16383
    d_w_h[i]         = __float2half(tw[i]);
    d_w_h[16384 + i] = __float2half(pw[i]);
    d_w_h[32768 + i] = __float2half(gw[i]);
    d_w2_h[i]        = __float2half(w2[i]);
}

// ============== Kernel 1: projections (fp16 single-pass mma) ==============
// CTA 256 thr; M=64(ci), N=128(n), K=256 in 2 chunks of 128.
// smem: ws [64][136] fp16 (272B rows), xs [128][136] fp16
constexpr int PJ_WS   = 0;
constexpr int PJ_XS   = 17408;
constexpr int PJ_SMEM = 52224;

__global__ __launch_bounds__(256) void proj_kernel(
    const float* __restrict__ tb, const float* __restrict__ pb,
    const float* __restrict__ gb)
{
    extern __shared__ char sm[];
    const uint32_t sb = smem_u32(sm);
    const int tid = threadIdx.x;
    const int wid = tid >> 5, lane = tid & 31;
    const int nt = blockIdx.x, b = blockIdx.y, pj = blockIdx.z;
    const int lr = lane >> 2, lc = lane & 3;

    const __half* wh = d_w_h + pj * CI_ * C_;
    const __half* xh = d_x_h + (size_t)b * C_ * N_ + nt * 128;

    const int mi = wid & 3, nh = wid >> 2;
    const int amr = (lane & 7) + ((lane >> 3) & 1) * 8;   // A non-trans m-offset
    const int akc = (lane >> 4) * 8;                       // A non-trans k-offset
    const int bkr = ((lane >> 3) & 1) * 8 + (lane & 7);    // B trans k(row)-offset
    const int bnc = (lane >> 4) * 8;                       // B trans n(col)-offset

    float acc[8][4];
    #pragma unroll
    for (int i = 0; i < 8; i++)
        #pragma unroll
        for (int j = 0; j < 4; j++) acc[i][j] = 0.f;

    for (int ch = 0; ch < 2; ch++) {
        __syncthreads();
        // W chunk [64 ci][128 c]: 256B/row -> 1024 16B chunks
        #pragma unroll
        for (int j = 0; j < 4; j++) {
            int idx = tid + j * 256;
            int row = idx >> 4, c16 = idx & 15;
            *(uint4*)(sm + PJ_WS + row * 272 + c16 * 16) =
                *(const uint4*)(wh + (size_t)row * C_ + ch * 128 + c16 * 8);
        }
        // X chunk [128 c][128 n]: 2048 chunks
        #pragma unroll
        for (int j = 0; j < 8; j++) {
            int idx = tid + j * 256;
            int row = idx >> 4, c16 = idx & 15;
            *(uint4*)(sm + PJ_XS + row * 272 + c16 * 16) =
                *(const uint4*)(xh + (size_t)(ch * 128 + row) * N_ + c16 * 8);
        }
        __syncthreads();

        #pragma unroll
        for (int ks = 0; ks < 8; ks++) {
            uint32_t a[4];
            ldmx4(a, sb + PJ_WS + ((mi * 16 + amr) * 136 + ks * 16 + akc) * 2);
            #pragma unroll
            for (int nf4 = 0; nf4 < 4; nf4++) {
                uint32_t bb[4];
                ldmx4t(bb, sb + PJ_XS +
                           ((ks * 16 + bkr) * 136 + nh * 64 + nf4 * 16 + bnc) * 2);
                mma_f16(acc[2 * nf4],     a, bb);
                mma_f16(acc[2 * nf4 + 1], a, bb + 2);
            }
        }
    }

    const float* bias = (pj == 0) ? tb : (pj == 1) ? pb : gb;
    const int ci0 = mi * 16 + lr;
    const float bv0 = bias[ci0], bv1 = bias[ci0 + 8];

    if (pj == 2) {
        __nv_bfloat16* out = d_g + (size_t)b * CI_ * N_;
        #pragma unroll
        for (int nf = 0; nf < 8; nf++) {
            size_t n = (size_t)nt * 128 + nh * 64 + nf * 8 + lc * 2;
            *(uint32_t*)(out + (size_t)ci0 * N_ + n) =
                pack_bf16x2(acc[nf][0] + bv0, acc[nf][1] + bv0);
            *(uint32_t*)(out + (size_t)(ci0 + 8) * N_ + n) =
                pack_bf16x2(acc[nf][2] + bv1, acc[nf][3] + bv1);
        }
    } else {
        // theta gets pre-scaled by log2e (so attention exp is a bare ex2)
        const float sc = (pj == 0) ? LOG2E : 1.f;
        __half* out = (pj == 0 ? d_th : d_ph) + (size_t)b * CI_ * N_;
        #pragma unroll
        for (int nf = 0; nf < 8; nf++) {
            size_t n = (size_t)nt * 128 + nh * 64 + nf * 8 + lc * 2;
            *(uint32_t*)(out + (size_t)ci0 * N_ + n) =
                pack_f16x2((acc[nf][0] + bv0) * sc, (acc[nf][1] + bv0) * sc);
            *(uint32_t*)(out + (size_t)(ci0 + 8) * N_ + n) =
                pack_f16x2((acc[nf][2] + bv1) * sc, (acc[nf][3] + bv1) * sc);
        }
    }
}

// ============== Kernel 2: flash attention, fp16 S, 4-stage cp.async ==============
// CTA 256 thr / 8 warps, 128 queries, 64 key tiles of 64.
// Stage = phi fp16 [64ci][64k] + g bf16 [64ci][64k], rows 144B (stride 72 elems).
constexpr int AT_TILE  = 9216;       // 64*144
constexpr int AT_STAGE = 18432;      // 2 tiles
constexpr int AT_SMEM  = 73728;      // 4 stages

__device__ __forceinline__ void attn_stage_issue(
    uint32_t sbase, const __half* ph, const __nv_bfloat16* gg, int kt, int tid)
{
    #pragma unroll
    for (int j = 0; j < 2; j++) {
        int idx = tid + j * 256;             // 0..511
        int row = idx >> 3, c16 = idx & 7;
        uint32_t so = row * 144 + c16 * 16;
        cp16(sbase + so,           ph + (size_t)row * N_ + kt * 64 + c16 * 8);
        cp16(sbase + AT_TILE + so, gg + (size_t)row * N_ + kt * 64 + c16 * 8);
    }
}

__global__ __launch_bounds__(256, 2) void attn_kernel()
{
    extern __shared__ char sm[];
    const uint32_t sb = smem_u32(sm);
    const int tid = threadIdx.x;
    const int wid = tid >> 5, lane = tid & 31;
    const int nt = blockIdx.x, b = blockIdx.y;
    const int lr = lane >> 2, lc = lane & 3;

    const __half* ph = d_ph + (size_t)b * CI_ * N_;
    const __nv_bfloat16* gg = d_g + (size_t)b * CI_ * N_;
    const __half* th = d_th + (size_t)b * CI_ * N_ + nt * 128;

    // ---- theta A-frags (fp16, log2e-scaled) staged through stages 0-1 region ----
    const int tkr = (lane >> 4) * 8 + (lane & 7);      // A trans k(row)
    const int tmc = ((lane >> 3) & 1) * 8;             // A trans m(col)
    uint32_t a[4][4];
    {
        // theta tile [64 ci][128 q] fp16, stride 136 elems (272B), 1024 chunks
        #pragma unroll
        for (int j = 0; j < 4; j++) {
            int idx = tid + j * 256;
            int row = idx >> 4, c16 = idx & 15;
            *(uint4*)(sm + row * 272 + c16 * 16) =
                *(const uint4*)(th + (size_t)row * N_ + c16 * 8);
        }
        __syncthreads();
        #pragma unroll
        for (int kc = 0; kc < 4; kc++)
            ldmx4t(a[kc], sb + ((kc * 16 + tkr) * 136 + wid * 16 + tmc) * 2);
        __syncthreads();   // done reading theta region before prefetch overwrites
    }

    // prefetch stages 0..2
    attn_stage_issue(sb,                ph, gg, 0, tid); cp_commit();
    attn_stage_issue(sb + AT_STAGE,     ph, gg, 1, tid); cp_commit();
    attn_stage_issue(sb + 2 * AT_STAGE, ph, gg, 2, tid); cp_commit();

    // lane maps for B frags
    const int bkr = ((lane >> 3) & 1) * 8 + (lane & 7);   // trans (phi)
    const int bnc = (lane >> 4) * 8;
    const int lmr = ((lane >> 4) << 3) + (lane & 7);      // non-trans (g)
    const int lmc = ((lane >> 3) & 1) * 8;

    float yacc[8][4];
    #pragma unroll
    for (int i = 0; i < 8; i++)
        #pragma unroll
        for (int j = 0; j < 4; j++) yacc[i][j] = 0.f;
    float rs0 = 0.f, rs1 = 0.f;

    for (int kt = 0; kt < 64; kt++) {
        cp_wait<2>();
        __syncthreads();
        if (kt + 3 < 64)
            attn_stage_issue(sb + ((kt + 3) & 3) * AT_STAGE, ph, gg, kt + 3, tid);
        cp_commit();   // uniform group count

        const uint32_t SB = sb + (kt & 3) * AT_STAGE;

        // ---- S' = (log2e*theta) . phi^T, single fp16 pass ----
        float s[8][4];
        #pragma unroll
        for (int i = 0; i < 8; i++)
            #pragma unroll
            for (int j = 0; j < 4; j++) s[i][j] = 0.f;

        #pragma unroll
        for (int kc = 0; kc < 4; kc++) {
            #pragma unroll
            for (int kyg = 0; kyg < 4; kyg++) {
                uint32_t bh[4];
                ldmx4t(bh, SB + ((kc * 16 + bkr) * 72 + kyg * 16 + bnc) * 2);
                mma_f16(s[2 * kyg],     a[kc], bh);
                mma_f16(s[2 * kyg + 1], a[kc], bh + 2);
            }
        }

        // ---- P = 2^{S'} (ex2), rowsum, pack P to bf16 ----
        uint32_t pa[4][4];
        #pragma unroll
        for (int i = 0; i < 8; i++) {
            float e0 = ex2f(s[i][0]);
            float e1 = ex2f(s[i][1]);
            float e2 = ex2f(s[i][2]);
            float e3 = ex2f(s[i][3]);
            rs0 += e0 + e1;
            rs1 += e2 + e3;
            pa[i >> 1][(i & 1) ? 2 : 0] = pack_bf16x2(e0, e1);
            pa[i >> 1][(i & 1) ? 3 : 1] = pack_bf16x2(e2, e3);
        }

        // ---- Y += P . g (bf16) ----
        #pragma unroll
        for (int kkc = 0; kkc < 4; kkc++) {
            #pragma unroll
            for (int cg = 0; cg < 4; cg++) {
                uint32_t bg[4];
                ldmx4(bg, SB + AT_TILE + ((cg * 16 + lmr) * 72 + kkc * 16 + lmc) * 2);
                mma_bf16(yacc[2 * cg],     pa[kkc], bg);
                mma_bf16(yacc[2 * cg + 1], pa[kkc], bg + 2);
            }
        }
    }

    rs0 += __shfl_xor_sync(0xFFFFFFFFu, rs0, 1);
    rs0 += __shfl_xor_sync(0xFFFFFFFFu, rs0, 2);
    rs1 += __shfl_xor_sync(0xFFFFFFFFu, rs1, 1);
    rs1 += __shfl_xor_sync(0xFFFFFFFFu, rs1, 2);
    const float i0 = 1.f / rs0, i1 = 1.f / rs1;

    // store y fp16 [b][n][ci]
    const int q0 = nt * 128 + wid * 16;
    __half* yp = d_y + ((size_t)b * N_ + q0) * CI_;
    #pragma unroll
    for (int nf = 0; nf < 8; nf++) {
        int c = nf * 8 + lc * 2;
        *(uint32_t*)(yp + (size_t)lr * CI_ + c) =
            pack_f16x2(yacc[nf][0] * i0, yacc[nf][1] * i0);
        *(uint32_t*)(yp + (size_t)(lr + 8) * CI_ + c) =
            pack_f16x2(yacc[nf][2] * i1, yacc[nf][3] * i1);
    }
}

// ============== Kernel 3: output conv + residual (fp16 single-pass) ==============
// grid (32 n-tiles of 128, 2 co-halves of 128, B). 256 thr.
constexpr int WC_W    = 0;       // [128 co][64 ci] fp16, stride 72
constexpr int WC_Y    = 18432;   // [128 n][64 ci] fp16
constexpr int WC_SMEM = 36864;

__global__ __launch_bounds__(256) void wconv_kernel(
    const float* __restrict__ x, const float* __restrict__ wb,
    float* __restrict__ out)
{
    extern __shared__ char sm[];
    const uint32_t sb = smem_u32(sm);
    const int tid = threadIdx.x;
    const int wid = tid >> 5, lane = tid & 31;
    const int nt = blockIdx.x, ct = blockIdx.y, b = blockIdx.z;
    const int lr = lane >> 2, lc = lane & 3;

    #pragma unroll
    for (int j = 0; j < 4; j++) {
        int idx = tid + j * 256;          // 0..1023
        int row = idx >> 3, c16 = idx & 7;
        uint32_t so = row * 144 + c16 * 16;
        *(uint4*)(sm + WC_W + so) =
            *(const uint4*)(d_w2_h + (size_t)(ct * 128 + row) * CI_ + c16 * 8);
        *(uint4*)(sm + WC_Y + so) =
            *(const uint4*)(d_y + ((size_t)b * N_ + nt * 128 + row) * CI_ + c16 * 8);
    }
    __syncthreads();

    const int mi = wid & 3, nh = wid >> 2;
    const int amr = (lane & 7) + ((lane >> 3) & 1) * 8;
    const int akc = (lane >> 4) * 8;
    const int lmr = ((lane >> 4) << 3) + (lane & 7);
    const int lmc = ((lane >> 3) & 1) * 8;

    float acc[2][8][4];
    #pragma unroll
    for (int m = 0; m < 2; m++)
        #pragma unroll
        for (int i = 0; i < 8; i++)
            #pragma unroll
            for (int j = 0; j < 4; j++) acc[m][i][j] = 0.f;

    #pragma unroll
    for (int ks = 0; ks < 4; ks++) {
        uint32_t ah[2][4];
        #pragma unroll
        for (int m = 0; m < 2; m++)
            ldmx4(ah[m], sb + WC_W + ((mi * 32 + m * 16 + amr) * 72 + ks * 16 + akc) * 2);
        #pragma unroll
        for (int nf4 = 0; nf4 < 4; nf4++) {
            uint32_t bh[4];
            ldmx4(bh, sb + WC_Y + ((nh * 64 + nf4 * 16 + lmr) * 72 + ks * 16 + lmc) * 2);
            #pragma unroll
            for (int m = 0; m < 2; m++) {
                mma_f16(acc[m][2 * nf4],     ah[m], bh);
                mma_f16(acc[m][2 * nf4 + 1], ah[m], bh + 2);
            }
        }
    }

    #pragma unroll
    for (int m = 0; m < 2; m++) {
        int co0 = ct * 128 + mi * 32 + m * 16 + lr;
        float bv0 = wb[co0], bv1 = wb[co0 + 8];
        #pragma unroll
        for (int nf = 0; nf < 8; nf++) {
            size_t n = (size_t)nt * 128 + nh * 64 + nf * 8 + lc * 2;
            size_t base0 = ((size_t)b * C_ + co0) * N_ + n;
            size_t base1 = ((size_t)b * C_ + co0 + 8) * N_ + n;
            float2 x0 = *(const float2*)(x + base0);
            float2 x1 = *(const float2*)(x + base1);
            *(float2*)(out + base0) =
                make_float2(acc[m][nf][0] + bv0 + x0.x, acc[m][nf][1] + bv0 + x0.y);
            *(float2*)(out + base1) =
                make_float2(acc[m][nf][2] + bv1 + x1.x, acc[m][nf][3] + bv1 + x1.y);
        }
    }
}

// ---------------------------------------------------------------------------
extern "C" void kernel_launch(void* const* d_in, const int* in_sizes, int n_in,
                              void* d_out, int out_size)
{
    const float* x  = (const float*)d_in[0];
    const float* gw = (const float*)d_in[1];
    const float* gb = (const float*)d_in[2];
    const float* tw = (const float*)d_in[3];
    const float* tb = (const float*)d_in[4];
    const float* pw = (const float*)d_in[5];
    const float* pb = (const float*)d_in[6];
    const float* ww = (const float*)d_in[7];
    const float* wb = (const float*)d_in[8];
    float* out = (float*)d_out;

    cudaFuncSetAttribute(proj_kernel,  cudaFuncAttributeMaxDynamicSharedMemorySize, PJ_SMEM);
    cudaFuncSetAttribute(attn_kernel,  cudaFuncAttributeMaxDynamicSharedMemorySize, AT_SMEM);
    cudaFuncSetAttribute(wconv_kernel, cudaFuncAttributeMaxDynamicSharedMemorySize, WC_SMEM);

    split_x_kernel<<<4096, 512>>>(x);
    split_w_kernel<<<64, 256>>>(tw, pw, gw, ww);
    proj_kernel<<<dim3(N_ / 128, B_, 3), 256, PJ_SMEM>>>(tb, pb, gb);
    attn_kernel<<<dim3(N_ / 128, B_), 256, AT_SMEM>>>();
    wconv_kernel<<<dim3(N_ / 128, 2, B_), 256, WC_SMEM>>>(x, wb, out);
}

// round 7
// speedup vs baseline: 7.7580x; 1.4873x over previous
#include <cuda_runtime.h>
#include <cuda_bf16.h>
#include <cuda_fp16.h>
#include <cstdint>

// Problem constants
constexpr int B_  = 8;
constexpr int C_  = 256;
constexpr int CI_ = 64;
constexpr int N_  = 4096;   // H*W
constexpr float LOG2E = 1.4426950408889634f;

// ---------------- scratch (device globals: allocation-free rule) ----------------
__device__ __half d_x_h [B_ * C_ * N_];   // x fp16 [b][c][n]
__device__ __half d_w_h [3 * CI_ * C_];   // proj weights fp16: theta, phi, g
__device__ __half d_w2_h[C_ * CI_];       // output conv weight fp16 [co][ci]
__device__ __half d_th  [B_ * CI_ * N_];  // theta fp16 (pre-scaled by log2e) [b][ci][n]
__device__ __half d_ph  [B_ * CI_ * N_];  // phi fp16 [b][ci][n]
__device__ __nv_bfloat16 d_g[B_ * CI_ * N_];  // g bf16 [b][ci][n]
__device__ __half d_y   [B_ * N_ * CI_];  // attention out fp16 [b][n][ci]

// ---------------- helpers ----------------
__device__ __forceinline__ uint32_t smem_u32(const void* p) {
    uint32_t a;
    asm("{ .reg .u64 t; cvta.to.shared.u64 t, %1; cvt.u32.u64 %0, t; }" : "=r"(a) : "l"(p));
    return a;
}
__device__ __forceinline__ void mma_bf16(float* c, const uint32_t* a, const uint32_t* b) {
    asm volatile(
        "mma.sync.aligned.m16n8k16.row.col.f32.bf16.bf16.f32 "
        "{%0,%1,%2,%3}, {%4,%5,%6,%7}, {%8,%9}, {%0,%1,%2,%3};"
        : "+f"(c[0]), "+f"(c[1]), "+f"(c[2]), "+f"(c[3])
        : "r"(a[0]), "r"(a[1]), "r"(a[2]), "r"(a[3]), "r"(b[0]), "r"(b[1]));
}
__device__ __forceinline__ void mma_f16(float* c, const uint32_t* a, const uint32_t* b) {
    asm volatile(
        "mma.sync.aligned.m16n8k16.row.col.f32.f16.f16.f32 "
        "{%0,%1,%2,%3}, {%4,%5,%6,%7}, {%8,%9}, {%0,%1,%2,%3};"
        : "+f"(c[0]), "+f"(c[1]), "+f"(c[2]), "+f"(c[3])
        : "r"(a[0]), "r"(a[1]), "r"(a[2]), "r"(a[3]), "r"(b[0]), "r"(b[1]));
}
__device__ __forceinline__ void ldmx4(uint32_t* r, uint32_t addr) {
    asm volatile("ldmatrix.sync.aligned.m8n8.x4.shared.b16 {%0,%1,%2,%3}, [%4];"
                 : "=r"(r[0]), "=r"(r[1]), "=r"(r[2]), "=r"(r[3]) : "r"(addr));
}
__device__ __forceinline__ void ldmx4t(uint32_t* r, uint32_t addr) {
    asm volatile("ldmatrix.sync.aligned.m8n8.x4.trans.shared.b16 {%0,%1,%2,%3}, [%4];"
                 : "=r"(r[0]), "=r"(r[1]), "=r"(r[2]), "=r"(r[3]) : "r"(addr));
}
__device__ __forceinline__ uint32_t pack_bf16x2(float lo, float hi) {
    uint32_t r;
    asm("cvt.rn.bf16x2.f32 %0, %1, %2;" : "=r"(r) : "f"(hi), "f"(lo));
    return r;
}
__device__ __forceinline__ uint32_t pack_f16x2(float lo, float hi) {
    uint32_t r;
    asm("cvt.rn.f16x2.f32 %0, %1, %2;" : "=r"(r) : "f"(hi), "f"(lo));
    return r;
}
__device__ __forceinline__ float ex2f(float x) {
    float r;
    asm("ex2.approx.ftz.f32 %0, %1;" : "=f"(r) : "f"(x));
    return r;
}
__device__ __forceinline__ void cp16(uint32_t s, const void* g) {
    asm volatile("cp.async.cg.shared.global [%0], [%1], 16;" :: "r"(s), "l"(g));
}
__device__ __forceinline__ void cp_commit() { asm volatile("cp.async.commit_group;"); }
template <int n> __device__ __forceinline__ void cp_wait() {
    asm volatile("cp.async.wait_group %0;" :: "n"(n));
}

// ============== Kernel 0a: x -> fp16 ==============
__global__ __launch_bounds__(512) void split_x_kernel(const float* __restrict__ x)
{
    int i = blockIdx.x * 512 + threadIdx.x;
    float4 v = ((const float4*)x)[i];
    uint2 o;
    o.x = pack_f16x2(v.x, v.y);
    o.y = pack_f16x2(v.z, v.w);
    ((uint2*)d_x_h)[i] = o;
}

// ============== Kernel 0b: weights -> fp16 ==============
__global__ __launch_bounds__(256) void split_w_kernel(
    const float* __restrict__ tw, const float* __restrict__ pw,
    const float* __restrict__ gw, const float* __restrict__ w2)
{
    int i = blockIdx.x * 256 + threadIdx.x;
    d_w_h[i]         = __float2half(tw[i]);
    d_w_h[16384 + i] = __float2half(pw[i]);
    d_w_h[32768 + i] = __float2half(gw[i]);
    d_w2_h[i]        = __float2half(w2[i]);
}

// ============== Kernel 1: projections (fp16 single-pass mma) ==============
constexpr int PJ_WS   = 0;
constexpr int PJ_XS   = 17408;
constexpr int PJ_SMEM = 52224;

__global__ __launch_bounds__(256) void proj_kernel(
    const float* __restrict__ tb, const float* __restrict__ pb,
    const float* __restrict__ gb)
{
    extern __shared__ char sm[];
    const uint32_t sb = smem_u32(sm);
    const int tid = threadIdx.x;
    const int wid = tid >> 5, lane = tid & 31;
    const int nt = blockIdx.x, b = blockIdx.y, pj = blockIdx.z;
    const int lr = lane >> 2, lc = lane & 3;

    const __half* wh = d_w_h + pj * CI_ * C_;
    const __half* xh = d_x_h + (size_t)b * C_ * N_ + nt * 128;

    const int mi = wid & 3, nh = wid >> 2;
    const int amr = (lane & 7) + ((lane >> 3) & 1) * 8;
    const int akc = (lane >> 4) * 8;
    const int bkr = ((lane >> 3) & 1) * 8 + (lane & 7);
    const int bnc = (lane >> 4) * 8;

    float acc[8][4];
    #pragma unroll
    for (int i = 0; i < 8; i++)
        #pragma unroll
        for (int j = 0; j < 4; j++) acc[i][j] = 0.f;

    for (int ch = 0; ch < 2; ch++) {
        __syncthreads();
        #pragma unroll
        for (int j = 0; j < 4; j++) {
            int idx = tid + j * 256;
            int row = idx >> 4, c16 = idx & 15;
            *(uint4*)(sm + PJ_WS + row * 272 + c16 * 16) =
                *(const uint4*)(wh + (size_t)row * C_ + ch * 128 + c16 * 8);
        }
        #pragma unroll
        for (int j = 0; j < 8; j++) {
            int idx = tid + j * 256;
            int row = idx >> 4, c16 = idx & 15;
            *(uint4*)(sm + PJ_XS + row * 272 + c16 * 16) =
                *(const uint4*)(xh + (size_t)(ch * 128 + row) * N_ + c16 * 8);
        }
        __syncthreads();

        #pragma unroll
        for (int ks = 0; ks < 8; ks++) {
            uint32_t a[4];
            ldmx4(a, sb + PJ_WS + ((mi * 16 + amr) * 136 + ks * 16 + akc) * 2);
            #pragma unroll
            for (int nf4 = 0; nf4 < 4; nf4++) {
                uint32_t bb[4];
                ldmx4t(bb, sb + PJ_XS +
                           ((ks * 16 + bkr) * 136 + nh * 64 + nf4 * 16 + bnc) * 2);
                mma_f16(acc[2 * nf4],     a, bb);
                mma_f16(acc[2 * nf4 + 1], a, bb + 2);
            }
        }
    }

    const float* bias = (pj == 0) ? tb : (pj == 1) ? pb : gb;
    const int ci0 = mi * 16 + lr;
    const float bv0 = bias[ci0], bv1 = bias[ci0 + 8];

    if (pj == 2) {
        __nv_bfloat16* out = d_g + (size_t)b * CI_ * N_;
        #pragma unroll
        for (int nf = 0; nf < 8; nf++) {
            size_t n = (size_t)nt * 128 + nh * 64 + nf * 8 + lc * 2;
            *(uint32_t*)(out + (size_t)ci0 * N_ + n) =
                pack_bf16x2(acc[nf][0] + bv0, acc[nf][1] + bv0);
            *(uint32_t*)(out + (size_t)(ci0 + 8) * N_ + n) =
                pack_bf16x2(acc[nf][2] + bv1, acc[nf][3] + bv1);
        }
    } else {
        const float sc = (pj == 0) ? LOG2E : 1.f;
        __half* out = (pj == 0 ? d_th : d_ph) + (size_t)b * CI_ * N_;
        #pragma unroll
        for (int nf = 0; nf < 8; nf++) {
            size_t n = (size_t)nt * 128 + nh * 64 + nf * 8 + lc * 2;
            *(uint32_t*)(out + (size_t)ci0 * N_ + n) =
                pack_f16x2((acc[nf][0] + bv0) * sc, (acc[nf][1] + bv0) * sc);
            *(uint32_t*)(out + (size_t)(ci0 + 8) * N_ + n) =
                pack_f16x2((acc[nf][2] + bv1) * sc, (acc[nf][3] + bv1) * sc);
        }
    }
}

// ============== Kernel 2: flash attention, 4-warp CTAs, occ 4, rotated key order ==============
// CTA 128 thr / 4 warps, 64 queries (16/warp), 64 key tiles of 64 (rotated start).
// Stage = phi fp16 [64ci][64k] + g bf16 [64ci][64k], rows 144B. 3 stages.
constexpr int AT_TILE   = 9216;       // 64*144
constexpr int AT_STAGE  = 18432;      // 2 tiles
constexpr int AT_SMEM   = 55296;      // 3 stages

__device__ __forceinline__ void attn_stage_issue(
    uint32_t sbase, const __half* ph, const __nv_bfloat16* gg, int koff, int tid)
{
    #pragma unroll
    for (int j = 0; j < 4; j++) {
        int idx = tid + j * 128;             // 0..511
        int row = idx >> 3, c16 = idx & 7;
        uint32_t so = row * 144 + c16 * 16;
        cp16(sbase + so,           ph + (size_t)row * N_ + koff + c16 * 8);
        cp16(sbase + AT_TILE + so, gg + (size_t)row * N_ + koff + c16 * 8);
    }
}

__global__ __launch_bounds__(128, 4) void attn_kernel()
{
    extern __shared__ char sm[];
    const uint32_t sb = smem_u32(sm);
    const int tid = threadIdx.x;
    const int wid = tid >> 5, lane = tid & 31;
    const int nt = blockIdx.x;   // 64-query tile (0..63)
    const int b  = blockIdx.y;
    const int lr = lane >> 2, lc = lane & 3;
    const int phase = (blockIdx.x & 3) << 4;   // rotated key-tile start: 0/16/32/48

    const __half* ph = d_ph + (size_t)b * CI_ * N_;
    const __nv_bfloat16* gg = d_g + (size_t)b * CI_ * N_;
    const __half* th = d_th + (size_t)b * CI_ * N_ + nt * 64;

    // ---- theta A-frags: stage [64 ci][64 q] fp16 through stage-0 region ----
    const int tkr = (lane >> 4) * 8 + (lane & 7);      // A trans k(row)
    const int tmc = ((lane >> 3) & 1) * 8;             // A trans m(col)
    uint32_t a[4][4];
    {
        #pragma unroll
        for (int j = 0; j < 4; j++) {
            int idx = tid + j * 128;                   // 0..511
            int row = idx >> 3, c16 = idx & 7;
            *(uint4*)(sm + row * 144 + c16 * 16) =
                *(const uint4*)(th + (size_t)row * N_ + c16 * 8);
        }
        __syncthreads();
        #pragma unroll
        for (int kc = 0; kc < 4; kc++)
            ldmx4t(a[kc], sb + ((kc * 16 + tkr) * 72 + wid * 16 + tmc) * 2);
        __syncthreads();
    }

    // prefetch stages 0..2 (logical tiles 0,1,2 -> physical rotated)
    attn_stage_issue(sb,                ph, gg, ((0 + phase) & 63) * 64, tid); cp_commit();
    attn_stage_issue(sb + AT_STAGE,     ph, gg, ((1 + phase) & 63) * 64, tid); cp_commit();
    attn_stage_issue(sb + 2 * AT_STAGE, ph, gg, ((2 + phase) & 63) * 64, tid); cp_commit();

    // lane maps for B frags
    const int bkr = ((lane >> 3) & 1) * 8 + (lane & 7);   // trans (phi)
    const int bnc = (lane >> 4) * 8;
    const int lmr = ((lane >> 4) << 3) + (lane & 7);      // non-trans (g)
    const int lmc = ((lane >> 3) & 1) * 8;

    float yacc[8][4];
    #pragma unroll
    for (int i = 0; i < 8; i++)
        #pragma unroll
        for (int j = 0; j < 4; j++) yacc[i][j] = 0.f;
    float rs0 = 0.f, rs1 = 0.f;

    int slot = 0;   // stage slot of logical tile kt (kt % 3)
    for (int kt = 0; kt < 64; kt++) {
        cp_wait<2>();
        __syncthreads();

        const uint32_t SB = sb + slot * AT_STAGE;

        // ---- S' = (log2e*theta) . phi^T, single fp16 pass ----
        float s[8][4];
        #pragma unroll
        for (int i = 0; i < 8; i++)
            #pragma unroll
            for (int j = 0; j < 4; j++) s[i][j] = 0.f;

        #pragma unroll
        for (int kc = 0; kc < 4; kc++) {
            #pragma unroll
            for (int kyg = 0; kyg < 4; kyg++) {
                uint32_t bh[4];
                ldmx4t(bh, SB + ((kc * 16 + bkr) * 72 + kyg * 16 + bnc) * 2);
                mma_f16(s[2 * kyg],     a[kc], bh);
                mma_f16(s[2 * kyg + 1], a[kc], bh + 2);
            }
        }

        // ---- P = 2^{S'}, rowsum, pack to bf16 ----
        uint32_t pa[4][4];
        #pragma unroll
        for (int i = 0; i < 8; i++) {
            float e0 = ex2f(s[i][0]);
            float e1 = ex2f(s[i][1]);
            float e2 = ex2f(s[i][2]);
            float e3 = ex2f(s[i][3]);
            rs0 += e0 + e1;
            rs1 += e2 + e3;
            pa[i >> 1][(i & 1) ? 2 : 0] = pack_bf16x2(e0, e1);
            pa[i >> 1][(i & 1) ? 3 : 1] = pack_bf16x2(e2, e3);
        }

        // ---- Y += P . g (bf16) ----
        #pragma unroll
        for (int kkc = 0; kkc < 4; kkc++) {
            #pragma unroll
            for (int cg = 0; cg < 4; cg++) {
                uint32_t bg[4];
                ldmx4(bg, SB + AT_TILE + ((cg * 16 + lmr) * 72 + kkc * 16 + lmc) * 2);
                mma_bf16(yacc[2 * cg],     pa[kkc], bg);
                mma_bf16(yacc[2 * cg + 1], pa[kkc], bg + 2);
            }
        }

        // ---- release slot, refill with logical tile kt+3 (same slot) ----
        __syncthreads();
        if (kt + 3 < 64)
            attn_stage_issue(SB, ph, gg, ((kt + 3 + phase) & 63) * 64, tid);
        cp_commit();   // uniform group count
        slot = (slot == 2) ? 0 : slot + 1;
    }

    rs0 += __shfl_xor_sync(0xFFFFFFFFu, rs0, 1);
    rs0 += __shfl_xor_sync(0xFFFFFFFFu, rs0, 2);
    rs1 += __shfl_xor_sync(0xFFFFFFFFu, rs1, 1);
    rs1 += __shfl_xor_sync(0xFFFFFFFFu, rs1, 2);
    const float i0 = 1.f / rs0, i1 = 1.f / rs1;

    // store y fp16 [b][n][ci]
    const int q0 = nt * 64 + wid * 16;
    __half* yp = d_y + ((size_t)b * N_ + q0) * CI_;
    #pragma unroll
    for (int nf = 0; nf < 8; nf++) {
        int c = nf * 8 + lc * 2;
        *(uint32_t*)(yp + (size_t)lr * CI_ + c) =
            pack_f16x2(yacc[nf][0] * i0, yacc[nf][1] * i0);
        *(uint32_t*)(yp + (size_t)(lr + 8) * CI_ + c) =
            pack_f16x2(yacc[nf][2] * i1, yacc[nf][3] * i1);
    }
}

// ============== Kernel 3: output conv + residual (fp16 single-pass) ==============
constexpr int WC_W    = 0;
constexpr int WC_Y    = 18432;
constexpr int WC_SMEM = 36864;

__global__ __launch_bounds__(256) void wconv_kernel(
    const float* __restrict__ x, const float* __restrict__ wb,
    float* __restrict__ out)
{
    extern __shared__ char sm[];
    const uint32_t sb = smem_u32(sm);
    const int tid = threadIdx.x;
    const int wid = tid >> 5, lane = tid & 31;
    const int nt = blockIdx.x, ct = blockIdx.y, b = blockIdx.z;
    const int lr = lane >> 2, lc = lane & 3;

    #pragma unroll
    for (int j = 0; j < 4; j++) {
        int idx = tid + j * 256;
        int row = idx >> 3, c16 = idx & 7;
        uint32_t so = row * 144 + c16 * 16;
        *(uint4*)(sm + WC_W + so) =
            *(const uint4*)(d_w2_h + (size_t)(ct * 128 + row) * CI_ + c16 * 8);
        *(uint4*)(sm + WC_Y + so) =
            *(const uint4*)(d_y + ((size_t)b * N_ + nt * 128 + row) * CI_ + c16 * 8);
    }
    __syncthreads();

    const int mi = wid & 3, nh = wid >> 2;
    const int amr = (lane & 7) + ((lane >> 3) & 1) * 8;
    const int akc = (lane >> 4) * 8;
    const int lmr = ((lane >> 4) << 3) + (lane & 7);
    const int lmc = ((lane >> 3) & 1) * 8;

    float acc[2][8][4];
    #pragma unroll
    for (int m = 0; m < 2; m++)
        #pragma unroll
        for (int i = 0; i < 8; i++)
            #pragma unroll
            for (int j = 0; j < 4; j++) acc[m][i][j] = 0.f;

    #pragma unroll
    for (int ks = 0; ks < 4; ks++) {
        uint32_t ah[2][4];
        #pragma unroll
        for (int m = 0; m < 2; m++)
            ldmx4(ah[m], sb + WC_W + ((mi * 32 + m * 16 + amr) * 72 + ks * 16 + akc) * 2);
        #pragma unroll
        for (int nf4 = 0; nf4 < 4; nf4++) {
            uint32_t bh[4];
            ldmx4(bh, sb + WC_Y + ((nh * 64 + nf4 * 16 + lmr) * 72 + ks * 16 + lmc) * 2);
            #pragma unroll
            for (int m = 0; m < 2; m++) {
                mma_f16(acc[m][2 * nf4],     ah[m], bh);
                mma_f16(acc[m][2 * nf4 + 1], ah[m], bh + 2);
            }
        }
    }

    #pragma unroll
    for (int m = 0; m < 2; m++) {
        int co0 = ct * 128 + mi * 32 + m * 16 + lr;
        float bv0 = wb[co0], bv1 = wb[co0 + 8];
        #pragma unroll
        for (int nf = 0; nf < 8; nf++) {
            size_t n = (size_t)nt * 128 + nh * 64 + nf * 8 + lc * 2;
            size_t base0 = ((size_t)b * C_ + co0) * N_ + n;
            size_t base1 = ((size_t)b * C_ + co0 + 8) * N_ + n;
            float2 x0 = *(const float2*)(x + base0);
            float2 x1 = *(const float2*)(x + base1);
            *(float2*)(out + base0) =
                make_float2(acc[m][nf][0] + bv0 + x0.x, acc[m][nf][1] + bv0 + x0.y);
            *(float2*)(out + base1) =
                make_float2(acc[m][nf][2] + bv1 + x1.x, acc[m][nf][3] + bv1 + x1.y);
        }
    }
}

// ---------------------------------------------------------------------------
extern "C" void kernel_launch(void* const* d_in, const int* in_sizes, int n_in,
                              void* d_out, int out_size)
{
    const float* x  = (const float*)d_in[0];
    const float* gw = (const float*)d_in[1];
    const float* gb = (const float*)d_in[2];
    const float* tw = (const float*)d_in[3];
    const float* tb = (const float*)d_in[4];
    const float* pw = (const float*)d_in[5];
    const float* pb = (const float*)d_in[6];
    const float* ww = (const float*)d_in[7];
    const float* wb = (const float*)d_in[8];
    float* out = (float*)d_out;

    cudaFuncSetAttribute(proj_kernel,  cudaFuncAttributeMaxDynamicSharedMemorySize, PJ_SMEM);
    cudaFuncSetAttribute(attn_kernel,  cudaFuncAttributeMaxDynamicSharedMemorySize, AT_SMEM);
    cudaFuncSetAttribute(wconv_kernel, cudaFuncAttributeMaxDynamicSharedMemorySize, WC_SMEM);

    split_x_kernel<<<4096, 512>>>(x);
    split_w_kernel<<<64, 256>>>(tw, pw, gw, ww);
    proj_kernel<<<dim3(N_ / 128, B_, 3), 256, PJ_SMEM>>>(tb, pb, gb);
    attn_kernel<<<dim3(N_ / 64, B_), 128, AT_SMEM>>>();
    wconv_kernel<<<dim3(N_ / 128, 2, B_), 256, WC_SMEM>>>(x, wb, out);
}

// round 8
// speedup vs baseline: 8.4331x; 1.0870x over previous
#include <cuda_runtime.h>
#include <cuda_bf16.h>
#include <cuda_fp16.h>
#include <cstdint>

// Problem constants
constexpr int B_  = 8;
constexpr int C_  = 256;
constexpr int CI_ = 64;
constexpr int N_  = 4096;   // H*W
constexpr float LOG2E = 1.4426950408889634f;
constexpr uint32_t H2_OFF16 = 0x4C004C00u;   // f16x2 {16.0, 16.0}

// ---------------- scratch (device globals: allocation-free rule) ----------------
__device__ __half d_x_h [B_ * C_ * N_];   // x fp16 [b][c][n]
__device__ __half d_w_h [3 * CI_ * C_];   // proj weights fp16: theta, phi, g
__device__ __half d_w2_h[C_ * CI_];       // output conv weight fp16 [co][ci]
__device__ __half d_th  [B_ * CI_ * N_];  // theta fp16 (pre-scaled by log2e) [b][ci][n]
__device__ __half d_ph  [B_ * CI_ * N_];  // phi fp16 [b][ci][n]
__device__ __half d_g   [B_ * CI_ * N_];  // g fp16 [b][ci][n]
__device__ __half d_y   [B_ * N_ * CI_];  // attention out fp16 [b][n][ci]

// ---------------- helpers ----------------
__device__ __forceinline__ uint32_t smem_u32(const void* p) {
    uint32_t a;
    asm("{ .reg .u64 t; cvta.to.shared.u64 t, %1; cvt.u32.u64 %0, t; }" : "=r"(a) : "l"(p));
    return a;
}
__device__ __forceinline__ void mma_f16(float* c, const uint32_t* a, const uint32_t* b) {
    asm volatile(
        "mma.sync.aligned.m16n8k16.row.col.f32.f16.f16.f32 "
        "{%0,%1,%2,%3}, {%4,%5,%6,%7}, {%8,%9}, {%0,%1,%2,%3};"
        : "+f"(c[0]), "+f"(c[1]), "+f"(c[2]), "+f"(c[3])
        : "r"(a[0]), "r"(a[1]), "r"(a[2]), "r"(a[3]), "r"(b[0]), "r"(b[1]));
}
__device__ __forceinline__ void ldmx4(uint32_t* r, uint32_t addr) {
    asm volatile("ldmatrix.sync.aligned.m8n8.x4.shared.b16 {%0,%1,%2,%3}, [%4];"
                 : "=r"(r[0]), "=r"(r[1]), "=r"(r[2]), "=r"(r[3]) : "r"(addr));
}
__device__ __forceinline__ void ldmx4t(uint32_t* r, uint32_t addr) {
    asm volatile("ldmatrix.sync.aligned.m8n8.x4.trans.shared.b16 {%0,%1,%2,%3}, [%4];"
                 : "=r"(r[0]), "=r"(r[1]), "=r"(r[2]), "=r"(r[3]) : "r"(addr));
}
__device__ __forceinline__ uint32_t pack_f16x2(float lo, float hi) {
    uint32_t r;
    asm("cvt.rn.f16x2.f32 %0, %1, %2;" : "=r"(r) : "f"(hi), "f"(lo));
    return r;
}
// p = 2^(x - 16) elementwise on f16x2 (input packed from fp32 logits)
__device__ __forceinline__ uint32_t exp2_off16(uint32_t h2) {
    asm("sub.f16x2 %0, %0, %1;" : "+r"(h2) : "r"(H2_OFF16));
    asm("ex2.approx.f16x2 %0, %0;" : "+r"(h2));
    return h2;
}
__device__ __forceinline__ uint32_t hadd2u(uint32_t a, uint32_t b) {
    uint32_t r;
    asm("add.f16x2 %0, %1, %2;" : "=r"(r) : "r"(a), "r"(b));
    return r;
}
__device__ __forceinline__ float2 h2_to_f2(uint32_t h2) {
    __half2 h = *reinterpret_cast<__half2*>(&h2);
    return __half22float2(h);
}
__device__ __forceinline__ void cp16(uint32_t s, const void* g) {
    asm volatile("cp.async.cg.shared.global [%0], [%1], 16;" :: "r"(s), "l"(g));
}
__device__ __forceinline__ void cp_commit() { asm volatile("cp.async.commit_group;"); }
template <int n> __device__ __forceinline__ void cp_wait() {
    asm volatile("cp.async.wait_group %0;" :: "n"(n));
}

// ============== Kernel 0: x -> fp16 (blocks < 4096) and weights -> fp16 ==============
__global__ __launch_bounds__(512) void split_kernel(
    const float* __restrict__ x,
    const float* __restrict__ tw, const float* __restrict__ pw,
    const float* __restrict__ gw, const float* __restrict__ w2)
{
    if (blockIdx.x < 4096) {
        int i = blockIdx.x * 512 + threadIdx.x;
        float4 v = ((const float4*)x)[i];
        uint2 o;
        o.x = pack_f16x2(v.x, v.y);
        o.y = pack_f16x2(v.z, v.w);
        ((uint2*)d_x_h)[i] = o;
    } else {
        int i = (blockIdx.x - 4096) * 512 + threadIdx.x;   // 0..16383
        d_w_h[i]         = __float2half(tw[i]);
        d_w_h[16384 + i] = __float2half(pw[i]);
        d_w_h[32768 + i] = __float2half(gw[i]);
        d_w2_h[i]        = __float2half(w2[i]);
    }
}

// ============== Kernel 1: projections (fp16 single-pass mma) ==============
constexpr int PJ_WS   = 0;
constexpr int PJ_XS   = 17408;
constexpr int PJ_SMEM = 52224;

__global__ __launch_bounds__(256) void proj_kernel(
    const float* __restrict__ tb, const float* __restrict__ pb,
    const float* __restrict__ gb)
{
    extern __shared__ char sm[];
    const uint32_t sb = smem_u32(sm);
    const int tid = threadIdx.x;
    const int wid = tid >> 5, lane = tid & 31;
    const int nt = blockIdx.x, b = blockIdx.y, pj = blockIdx.z;
    const int lr = lane >> 2, lc = lane & 3;

    const __half* wh = d_w_h + pj * CI_ * C_;
    const __half* xh = d_x_h + (size_t)b * C_ * N_ + nt * 128;

    const int mi = wid & 3, nh = wid >> 2;
    const int amr = (lane & 7) + ((lane >> 3) & 1) * 8;
    const int akc = (lane >> 4) * 8;
    const int bkr = ((lane >> 3) & 1) * 8 + (lane & 7);
    const int bnc = (lane >> 4) * 8;

    float acc[8][4];
    #pragma unroll
    for (int i = 0; i < 8; i++)
        #pragma unroll
        for (int j = 0; j < 4; j++) acc[i][j] = 0.f;

    for (int ch = 0; ch < 2; ch++) {
        __syncthreads();
        #pragma unroll
        for (int j = 0; j < 4; j++) {
            int idx = tid + j * 256;
            int row = idx >> 4, c16 = idx & 15;
            *(uint4*)(sm + PJ_WS + row * 272 + c16 * 16) =
                *(const uint4*)(wh + (size_t)row * C_ + ch * 128 + c16 * 8);
        }
        #pragma unroll
        for (int j = 0; j < 8; j++) {
            int idx = tid + j * 256;
            int row = idx >> 4, c16 = idx & 15;
            *(uint4*)(sm + PJ_XS + row * 272 + c16 * 16) =
                *(const uint4*)(xh + (size_t)(ch * 128 + row) * N_ + c16 * 8);
        }
        __syncthreads();

        #pragma unroll
        for (int ks = 0; ks < 8; ks++) {
            uint32_t a[4];
            ldmx4(a, sb + PJ_WS + ((mi * 16 + amr) * 136 + ks * 16 + akc) * 2);
            #pragma unroll
            for (int nf4 = 0; nf4 < 4; nf4++) {
                uint32_t bb[4];
                ldmx4t(bb, sb + PJ_XS +
                           ((ks * 16 + bkr) * 136 + nh * 64 + nf4 * 16 + bnc) * 2);
                mma_f16(acc[2 * nf4],     a, bb);
                mma_f16(acc[2 * nf4 + 1], a, bb + 2);
            }
        }
    }

    const float* bias = (pj == 0) ? tb : (pj == 1) ? pb : gb;
    const int ci0 = mi * 16 + lr;
    const float bv0 = bias[ci0], bv1 = bias[ci0 + 8];
    const float sc = (pj == 0) ? LOG2E : 1.f;   // theta pre-scaled by log2e

    __half* out = (pj == 0 ? d_th : (pj == 1 ? d_ph : d_g)) + (size_t)b * CI_ * N_;
    #pragma unroll
    for (int nf = 0; nf < 8; nf++) {
        size_t n = (size_t)nt * 128 + nh * 64 + nf * 8 + lc * 2;
        *(uint32_t*)(out + (size_t)ci0 * N_ + n) =
            pack_f16x2((acc[nf][0] + bv0) * sc, (acc[nf][1] + bv0) * sc);
        *(uint32_t*)(out + (size_t)(ci0 + 8) * N_ + n) =
            pack_f16x2((acc[nf][2] + bv1) * sc, (acc[nf][3] + bv1) * sc);
    }
}

// ============== Kernel 2: flash attention, m32/warp, 2-warp CTAs, 2-stage ==============
// CTA 64 thr / 2 warps, each warp 32 q rows (2 A-frag rows) -> 64 q/CTA. Grid (64, B).
// Stage = phi fp16 [64ci][64k] + g fp16 [64ci][64k], rows 144B. 2 stages.
constexpr int AT_TILE  = 9216;       // 64*144
constexpr int AT_STAGE = 18432;      // 2 tiles
constexpr int AT_SMEM  = 36864;      // 2 stages

__device__ __forceinline__ void attn_stage_issue(
    uint32_t sbase, const __half* ph, const __half* gg, int koff, int tid)
{
    #pragma unroll
    for (int j = 0; j < 8; j++) {
        int idx = tid + j * 64;              // 0..511
        int row = idx >> 3, c16 = idx & 7;
        uint32_t so = row * 144 + c16 * 16;
        cp16(sbase + so,           ph + (size_t)row * N_ + koff + c16 * 8);
        cp16(sbase + AT_TILE + so, gg + (size_t)row * N_ + koff + c16 * 8);
    }
}

__global__ __launch_bounds__(64, 4) void attn_kernel()
{
    extern __shared__ char sm[];
    const uint32_t sb = smem_u32(sm);
    const int tid = threadIdx.x;
    const int wid = tid >> 5, lane = tid & 31;
    const int nt = blockIdx.x;   // 64-query tile (0..63)
    const int b  = blockIdx.y;
    const int lr = lane >> 2, lc = lane & 3;
    const int phase = (nt & 3) << 4;   // rotated key-tile start

    const __half* ph = d_ph + (size_t)b * CI_ * N_;
    const __half* gg = d_g  + (size_t)b * CI_ * N_;
    const __half* th = d_th + (size_t)b * CI_ * N_ + nt * 64;

    // ---- theta A-frags: stage [64 ci][64 q] fp16 through stage-0 region ----
    const int tkr = (lane >> 4) * 8 + (lane & 7);      // A trans k(row)
    const int tmc = ((lane >> 3) & 1) * 8;             // A trans m(col)
    uint32_t a[4][2][4];   // [kc][arow][frag]
    {
        #pragma unroll
        for (int j = 0; j < 8; j++) {
            int idx = tid + j * 64;                    // 0..511
            int row = idx >> 3, c16 = idx & 7;
            *(uint4*)(sm + row * 144 + c16 * 16) =
                *(const uint4*)(th + (size_t)row * N_ + c16 * 8);
        }
        __syncthreads();
        #pragma unroll
        for (int kc = 0; kc < 4; kc++)
            #pragma unroll
            for (int ar = 0; ar < 2; ar++)
                ldmx4t(a[kc][ar],
                       sb + ((kc * 16 + tkr) * 72 + wid * 32 + ar * 16 + tmc) * 2);
        __syncthreads();
    }

    // prefetch stages 0, 1
    attn_stage_issue(sb,            ph, gg, ((0 + phase) & 63) * 64, tid); cp_commit();
    attn_stage_issue(sb + AT_STAGE, ph, gg, ((1 + phase) & 63) * 64, tid); cp_commit();

    // lane maps for B frags
    const int bkr = ((lane >> 3) & 1) * 8 + (lane & 7);   // trans (phi)
    const int bnc = (lane >> 4) * 8;
    const int lmr = ((lane >> 4) << 3) + (lane & 7);      // non-trans (g)
    const int lmc = ((lane >> 3) & 1) * 8;

    float yacc[2][8][4];
    #pragma unroll
    for (int ar = 0; ar < 2; ar++)
        #pragma unroll
        for (int i = 0; i < 8; i++)
            #pragma unroll
            for (int j = 0; j < 4; j++) yacc[ar][i][j] = 0.f;
    float rs[2][2] = {{0.f, 0.f}, {0.f, 0.f}};

    for (int kt = 0; kt < 64; kt++) {
        cp_wait<1>();
        __syncthreads();

        const uint32_t SB = sb + (kt & 1) * AT_STAGE;

        #pragma unroll
        for (int h = 0; h < 2; h++) {          // key halves of 32
            // ---- S' = (log2e*theta) . phi^T, fp32 acc ----
            float s[2][4][4];
            #pragma unroll
            for (int ar = 0; ar < 2; ar++)
                #pragma unroll
                for (int i = 0; i < 4; i++)
                    #pragma unroll
                    for (int j = 0; j < 4; j++) s[ar][i][j] = 0.f;

            #pragma unroll
            for (int kc = 0; kc < 4; kc++) {
                #pragma unroll
                for (int kyg = 0; kyg < 2; kyg++) {
                    uint32_t bh[4];
                    ldmx4t(bh, SB + ((kc * 16 + bkr) * 72 + h * 32 + kyg * 16 + bnc) * 2);
                    #pragma unroll
                    for (int ar = 0; ar < 2; ar++) {
                        mma_f16(s[ar][2 * kyg],     a[kc][ar], bh);
                        mma_f16(s[ar][2 * kyg + 1], a[kc][ar], bh + 2);
                    }
                }
            }

            // ---- P = 2^(S'-16) in f16 + rowsum ----
            uint32_t pe[2][4][2];
            #pragma unroll
            for (int ar = 0; ar < 2; ar++) {
                #pragma unroll
                for (int j = 0; j < 4; j++) {
                    pe[ar][j][0] = exp2_off16(pack_f16x2(s[ar][j][0], s[ar][j][1]));
                    pe[ar][j][1] = exp2_off16(pack_f16x2(s[ar][j][2], s[ar][j][3]));
                }
                uint32_t t0 = hadd2u(hadd2u(pe[ar][0][0], pe[ar][1][0]),
                                     hadd2u(pe[ar][2][0], pe[ar][3][0]));
                uint32_t t1 = hadd2u(hadd2u(pe[ar][0][1], pe[ar][1][1]),
                                     hadd2u(pe[ar][2][1], pe[ar][3][1]));
                float2 f0 = h2_to_f2(t0), f1 = h2_to_f2(t1);
                rs[ar][0] += f0.x + f0.y;
                rs[ar][1] += f1.x + f1.y;
            }

            // ---- Y += P . g (f16 x f16, fp32 acc) ----
            #pragma unroll
            for (int kkc = 0; kkc < 2; kkc++) {
                #pragma unroll
                for (int cg = 0; cg < 4; cg++) {
                    uint32_t bg[4];
                    ldmx4(bg, SB + AT_TILE +
                              ((cg * 16 + lmr) * 72 + h * 32 + kkc * 16 + lmc) * 2);
                    #pragma unroll
                    for (int ar = 0; ar < 2; ar++) {
                        uint32_t pa[4] = { pe[ar][2 * kkc][0],     pe[ar][2 * kkc][1],
                                           pe[ar][2 * kkc + 1][0], pe[ar][2 * kkc + 1][1] };
                        mma_f16(yacc[ar][2 * cg],     pa, bg);
                        mma_f16(yacc[ar][2 * cg + 1], pa, bg + 2);
                    }
                }
            }
        }

        // ---- release slot, refill with tile kt+2 ----
        __syncthreads();
        if (kt + 2 < 64)
            attn_stage_issue(SB, ph, gg, ((kt + 2 + phase) & 63) * 64, tid);
        cp_commit();   // uniform group count
    }

    #pragma unroll
    for (int ar = 0; ar < 2; ar++)
        #pragma unroll
        for (int r = 0; r < 2; r++) {
            float v = rs[ar][r];
            v += __shfl_xor_sync(0xFFFFFFFFu, v, 1);
            v += __shfl_xor_sync(0xFFFFFFFFu, v, 2);
            rs[ar][r] = 1.f / v;
        }

    // store y fp16 [b][n][ci]
    #pragma unroll
    for (int ar = 0; ar < 2; ar++) {
        const int q0 = nt * 64 + wid * 32 + ar * 16;
        __half* yp = d_y + ((size_t)b * N_ + q0) * CI_;
        const float i0 = rs[ar][0], i1 = rs[ar][1];
        #pragma unroll
        for (int nf = 0; nf < 8; nf++) {
            int c = nf * 8 + lc * 2;
            *(uint32_t*)(yp + (size_t)lr * CI_ + c) =
                pack_f16x2(yacc[ar][nf][0] * i0, yacc[ar][nf][1] * i0);
            *(uint32_t*)(yp + (size_t)(lr + 8) * CI_ + c) =
                pack_f16x2(yacc[ar][nf][2] * i1, yacc[ar][nf][3] * i1);
        }
    }
}

// ============== Kernel 3: output conv + residual (fp16 single-pass) ==============
constexpr int WC_W    = 0;
constexpr int WC_Y    = 18432;
constexpr int WC_SMEM = 36864;

__global__ __launch_bounds__(256) void wconv_kernel(
    const float* __restrict__ x, const float* __restrict__ wb,
    float* __restrict__ out)
{
    extern __shared__ char sm[];
    const uint32_t sb = smem_u32(sm);
    const int tid = threadIdx.x;
    const int wid = tid >> 5, lane = tid & 31;
    const int nt = blockIdx.x, ct = blockIdx.y, b = blockIdx.z;
    const int lr = lane >> 2, lc = lane & 3;

    #pragma unroll
    for (int j = 0; j < 4; j++) {
        int idx = tid + j * 256;
        int row = idx >> 3, c16 = idx & 7;
        uint32_t so = row * 144 + c16 * 16;
        *(uint4*)(sm + WC_W + so) =
            *(const uint4*)(d_w2_h + (size_t)(ct * 128 + row) * CI_ + c16 * 8);
        *(uint4*)(sm + WC_Y + so) =
            *(const uint4*)(d_y + ((size_t)b * N_ + nt * 128 + row) * CI_ + c16 * 8);
    }
    __syncthreads();

    const int mi = wid & 3, nh = wid >> 2;
    const int amr = (lane & 7) + ((lane >> 3) & 1) * 8;
    const int akc = (lane >> 4) * 8;
    const int lmr = ((lane >> 4) << 3) + (lane & 7);
    const int lmc = ((lane >> 3) & 1) * 8;

    float acc[2][8][4];
    #pragma unroll
    for (int m = 0; m < 2; m++)
        #pragma unroll
        for (int i = 0; i < 8; i++)
            #pragma unroll
            for (int j = 0; j < 4; j++) acc[m][i][j] = 0.f;

    #pragma unroll
    for (int ks = 0; ks < 4; ks++) {
        uint32_t ah[2][4];
        #pragma unroll
        for (int m = 0; m < 2; m++)
            ldmx4(ah[m], sb + WC_W + ((mi * 32 + m * 16 + amr) * 72 + ks * 16 + akc) * 2);
        #pragma unroll
        for (int nf4 = 0; nf4 < 4; nf4++) {
            uint32_t bh[4];
            ldmx4(bh, sb + WC_Y + ((nh * 64 + nf4 * 16 + lmr) * 72 + ks * 16 + lmc) * 2);
            #pragma unroll
            for (int m = 0; m < 2; m++) {
                mma_f16(acc[m][2 * nf4],     ah[m], bh);
                mma_f16(acc[m][2 * nf4 + 1], ah[m], bh + 2);
            }
        }
    }

    #pragma unroll
    for (int m = 0; m < 2; m++) {
        int co0 = ct * 128 + mi * 32 + m * 16 + lr;
        float bv0 = wb[co0], bv1 = wb[co0 + 8];
        #pragma unroll
        for (int nf = 0; nf < 8; nf++) {
            size_t n = (size_t)nt * 128 + nh * 64 + nf * 8 + lc * 2;
            size_t base0 = ((size_t)b * C_ + co0) * N_ + n;
            size_t base1 = ((size_t)b * C_ + co0 + 8) * N_ + n;
            float2 x0 = *(const float2*)(x + base0);
            float2 x1 = *(const float2*)(x + base1);
            *(float2*)(out + base0) =
                make_float2(acc[m][nf][0] + bv0 + x0.x, acc[m][nf][1] + bv0 + x0.y);
            *(float2*)(out + base1) =
                make_float2(acc[m][nf][2] + bv1 + x1.x, acc[m][nf][3] + bv1 + x1.y);
        }
    }
}

// ---------------------------------------------------------------------------
extern "C" void kernel_launch(void* const* d_in, const int* in_sizes, int n_in,
                              void* d_out, int out_size)
{
    const float* x  = (const float*)d_in[0];
    const float* gw = (const float*)d_in[1];
    const float* gb = (const float*)d_in[2];
    const float* tw = (const float*)d_in[3];
    const float* tb = (const float*)d_in[4];
    const float* pw = (const float*)d_in[5];
    const float* pb = (const float*)d_in[6];
    const float* ww = (const float*)d_in[7];
    const float* wb = (const float*)d_in[8];
    float* out = (float*)d_out;

    cudaFuncSetAttribute(proj_kernel,  cudaFuncAttributeMaxDynamicSharedMemorySize, PJ_SMEM);
    cudaFuncSetAttribute(attn_kernel,  cudaFuncAttributeMaxDynamicSharedMemorySize, AT_SMEM);
    cudaFuncSetAttribute(wconv_kernel, cudaFuncAttributeMaxDynamicSharedMemorySize, WC_SMEM);

    split_kernel<<<4128, 512>>>(x, tw, pw, gw, ww);
    proj_kernel<<<dim3(N_ / 128, B_, 3), 256, PJ_SMEM>>>(tb, pb, gb);
    attn_kernel<<<dim3(N_ / 64, B_), 64, AT_SMEM>>>();
    wconv_kernel<<<dim3(N_ / 128, 2, B_), 256, WC_SMEM>>>(x, wb, out);
}